// round 1
// baseline (speedup 1.0000x reference)
#include <cuda_runtime.h>
#include <cstdint>

// ---------------- problem constants (capacities) ----------------
#define NMAX   50000
#define DH     64
#define NG     64
#define NCLS   10

// ---------------- device scratch (no allocations allowed) -------
__device__ float4 g_A[NMAX * 16];      // ht buffer (pre-scaled linear output)
__device__ float4 g_B[NMAX * 16];      // agg buffer (init = self-loop term)
__device__ float4 g_C[NMAX * 16];      // layer activation
__device__ float  g_dis[NMAX];         // deg -> rsqrt(deg) in place
__device__ float4 g_pool[NG * 16];     // per-graph feature sums
__device__ float  g_cnt[NG];           // per-graph node counts
__device__ int    g_is32;              // 1 if indices are int32 on the wire

// ---------------- helpers ----------------
__device__ __forceinline__ int load_idx(const void* p, long long i, int is32) {
    if (is32) return ((const int*)p)[i];
    return (int)((const long long*)p)[i];
}

__device__ __forceinline__ void red_add_v4(float* addr, float4 v) {
    asm volatile("red.global.add.v4.f32 [%0], {%1,%2,%3,%4};"
                 :: "l"(addr), "f"(v.x), "f"(v.y), "f"(v.z), "f"(v.w)
                 : "memory");
}

// ---------------- kernels ----------------

// Detect index dtype: int64 data has all high words zero; int32 data does not.
__global__ void k_detect(const void* __restrict__ ei) {
    if (threadIdx.x == 0) {
        const long long* p = (const long long*)ei;
        int hi_nonzero = 0;
        for (int i = 0; i < 128; i++) {
            long long v = p[i];
            if ((unsigned long long)v > 0xFFFFFFFFull) hi_nonzero = 1;
        }
        g_is32 = hi_nonzero;
    }
}

// deg = 1 (self loop), pool = 0, cnt = 0
__global__ void k_init(int n) {
    int i = blockIdx.x * blockDim.x + threadIdx.x;
    if (i < n) g_dis[i] = 1.0f;
    if (i < NG * 16) g_pool[i] = make_float4(0.f, 0.f, 0.f, 0.f);
    if (i < NG) g_cnt[i] = 0.0f;
}

// deg[dst] += 1 over edges
__global__ void k_degcount(const void* __restrict__ ei, int E) {
    int e = blockIdx.x * blockDim.x + threadIdx.x;
    if (e >= E) return;
    int is32 = g_is32;
    int dst = load_idx(ei, (long long)E + e, is32);
    atomicAdd(&g_dis[dst], 1.0f);
}

// dis = rsqrt(deg) (deg >= 1 always due to self loop)
__global__ void k_rsqrt(int n) {
    int i = blockIdx.x * blockDim.x + threadIdx.x;
    if (i < n) g_dis[i] = rsqrtf(g_dis[i]);
}

// ht = (X @ W) * dis[row]; agg initialized to ht (self-loop term).
// 4 threads per row, 16 output columns each.
__global__ void k_gemm(const float* __restrict__ X, const float* __restrict__ W,
                       float* __restrict__ ht, float* __restrict__ agg, int n)
{
    __shared__ float4 Ws4[DH * 16];
    const float4* W4 = (const float4*)W;
    for (int i = threadIdx.x; i < DH * 16; i += blockDim.x) Ws4[i] = W4[i];
    __syncthreads();

    int row = blockIdx.x * 64 + (threadIdx.x >> 2);
    int q   = threadIdx.x & 3;            // column quarter (16 cols)
    if (row >= n) return;

    const float4* x4 = (const float4*)(X + (size_t)row * DH);
    float4 acc[4];
#pragma unroll
    for (int j = 0; j < 4; j++) acc[j] = make_float4(0.f, 0.f, 0.f, 0.f);

#pragma unroll
    for (int kk = 0; kk < 16; kk++) {
        float4 xk = x4[kk];
        float xs0 = xk.x, xs1 = xk.y, xs2 = xk.z, xs3 = xk.w;
#pragma unroll
        for (int c = 0; c < 4; c++) {
            float xv = (c == 0) ? xs0 : (c == 1) ? xs1 : (c == 2) ? xs2 : xs3;
            int k = kk * 4 + c;
#pragma unroll
            for (int j = 0; j < 4; j++) {
                float4 w = Ws4[k * 16 + q * 4 + j];
                acc[j].x += xv * w.x;
                acc[j].y += xv * w.y;
                acc[j].z += xv * w.z;
                acc[j].w += xv * w.w;
            }
        }
    }

    float ds = g_dis[row];
    float4* hto = (float4*)(ht  + (size_t)row * DH) + q * 4;
    float4* ago = (float4*)(agg + (size_t)row * DH) + q * 4;
#pragma unroll
    for (int j = 0; j < 4; j++) {
        float4 v = make_float4(acc[j].x * ds, acc[j].y * ds,
                               acc[j].z * ds, acc[j].w * ds);
        hto[j] = v;
        ago[j] = v;
    }
}

// agg[dst] += ht[src]   (norms already folded into ht / applied at finalize)
// 16 threads per edge, one float4 each.
__global__ void k_edge(const void* __restrict__ ei,
                       const float* __restrict__ ht,
                       float* __restrict__ agg, int E)
{
    int t = blockIdx.x * blockDim.x + threadIdx.x;
    int e = t >> 4;
    if (e >= E) return;
    int l = t & 15;
    int is32 = g_is32;
    int src = load_idx(ei, e, is32);
    int dst = load_idx(ei, (long long)E + e, is32);
    float4 v = ((const float4*)(ht + (size_t)src * DH))[l];
    red_add_v4(agg + (size_t)dst * DH + l * 4, v);
}

// out = relu(agg * dis[node] + b)
__global__ void k_fin(const float* __restrict__ agg, const float* __restrict__ b,
                      float* __restrict__ out, int n)
{
    int i = blockIdx.x * blockDim.x + threadIdx.x;
    if (i >= n * 16) return;
    int node = i >> 4, j4 = i & 15;
    float4 a = ((const float4*)agg)[i];
    float ds = g_dis[node];
    float4 bb = ((const float4*)b)[j4];
    float4 r;
    r.x = fmaxf(a.x * ds + bb.x, 0.f);
    r.y = fmaxf(a.y * ds + bb.y, 0.f);
    r.z = fmaxf(a.z * ds + bb.z, 0.f);
    r.w = fmaxf(a.w * ds + bb.w, 0.f);
    ((float4*)out)[i] = r;
}

// h2 = relu(agg * dis + b2); pool[batch[node]] += h2; cnt[batch[node]] += 1
__global__ void k_fin_pool(const float* __restrict__ agg, const float* __restrict__ b,
                           const void* __restrict__ batch, int n)
{
    int i = blockIdx.x * blockDim.x + threadIdx.x;
    if (i >= n * 16) return;
    int node = i >> 4, j4 = i & 15;
    float4 a = ((const float4*)agg)[i];
    float ds = g_dis[node];
    float4 bb = ((const float4*)b)[j4];
    float4 r;
    r.x = fmaxf(a.x * ds + bb.x, 0.f);
    r.y = fmaxf(a.y * ds + bb.y, 0.f);
    r.z = fmaxf(a.z * ds + bb.z, 0.f);
    r.w = fmaxf(a.w * ds + bb.w, 0.f);
    int is32 = g_is32;
    int gph = load_idx(batch, node, is32);
    red_add_v4((float*)g_pool + (size_t)gph * DH + j4 * 4, r);
    if (j4 == 0) atomicAdd(&g_cnt[gph], 1.0f);
}

// out[g, c] = (pool[g] / max(cnt,1)) @ Wfc + bfc
__global__ void k_fc(const float* __restrict__ Wfc, const float* __restrict__ bfc,
                     float* __restrict__ out)
{
    int t = threadIdx.x;
    if (t >= NG * NCLS) return;
    int gph = t / NCLS, c = t % NCLS;
    float inv = 1.0f / fmaxf(g_cnt[gph], 1.0f);
    const float* pr = (const float*)g_pool + (size_t)gph * DH;
    float acc = 0.f;
#pragma unroll
    for (int j = 0; j < DH; j++) acc += pr[j] * Wfc[j * NCLS + c];
    out[t] = acc * inv + bfc[c];
}

// ---------------- launcher ----------------
extern "C" void kernel_launch(void* const* d_in, const int* in_sizes, int n_in,
                              void* d_out, int out_size)
{
    const float* x   = (const float*)d_in[0];
    const void*  ei  = d_in[1];
    const void*  bat = d_in[2];
    const float* W1  = (const float*)d_in[3];
    const float* b1  = (const float*)d_in[4];
    const float* W2  = (const float*)d_in[5];
    const float* b2  = (const float*)d_in[6];
    const float* Wfc = (const float*)d_in[7];
    const float* bfc = (const float*)d_in[8];
    float* out = (float*)d_out;

    int n = in_sizes[0] / DH;       // nodes
    int E = in_sizes[1] / 2;        // edges

    float* A = (float*)g_A;  // need raw device pointers: use symbols directly
    // Note: __device__ arrays are directly addressable from kernels; we pass
    // their addresses by referencing the symbols inside kernels where possible.
    // For kernels taking pointers, take addresses via the symbols below.
    (void)A;

    // Resolve device-symbol addresses once per call (cheap, host-side, no alloc).
    static float* pA = nullptr; static float* pB = nullptr; static float* pC = nullptr;
    if (!pA) {
        void* tmp;
        cudaGetSymbolAddress(&tmp, g_A); pA = (float*)tmp;
        cudaGetSymbolAddress(&tmp, g_B); pB = (float*)tmp;
        cudaGetSymbolAddress(&tmp, g_C); pC = (float*)tmp;
    }

    const int TB = 256;

    k_detect<<<1, 32>>>(ei);
    k_init<<<(n + TB - 1) / TB, TB>>>(n);
    k_degcount<<<(E + TB - 1) / TB, TB>>>(ei, E);
    k_rsqrt<<<(n + TB - 1) / TB, TB>>>(n);

    int gemm_blocks = (n + 63) / 64;
    int edge_blocks = ((long long)E * 16 + TB - 1) / TB;
    int fin_blocks  = ((long long)n * 16 + TB - 1) / TB;

    // layer 1: ht1 -> A, agg1 -> B, h1 -> C
    k_gemm<<<gemm_blocks, TB>>>(x, W1, pA, pB, n);
    k_edge<<<edge_blocks, TB>>>(ei, pA, pB, E);
    k_fin <<<fin_blocks, TB>>>(pB, b1, pC, n);

    // layer 2: ht2 -> A, agg2 -> B, finalize + pool
    k_gemm<<<gemm_blocks, TB>>>(pC, W2, pA, pB, n);
    k_edge<<<edge_blocks, TB>>>(ei, pA, pB, E);
    k_fin_pool<<<fin_blocks, TB>>>(pB, b2, bat, n);

    k_fc<<<1, NG * NCLS>>>(Wfc, bfc, out);
}

// round 2
// speedup vs baseline: 1.4113x; 1.4113x over previous
#include <cuda_runtime.h>
#include <cstdint>

// ---------------- problem constants (capacities) ----------------
#define NMAX   50000
#define EMAX   1600000
#define DH     64
#define NG     64
#define NCLS   10
#define SCAN_B 256

// ---------------- device scratch (no allocations allowed) -------
__device__ float4 g_A[NMAX * 16];        // ht buffer (pre-scaled linear output)
__device__ float4 g_C[NMAX * 16];        // layer-1 activation
__device__ float  g_dis[NMAX];           // rsqrt(deg+1)
__device__ int    g_degi[NMAX];          // edge in-degree (no self loop)
__device__ int    g_rowtmp[NMAX];        // per-block exclusive scan
__device__ int    g_rowptr[NMAX];        // CSR row offsets
__device__ int    g_cursor[NMAX];        // fill cursors
__device__ int    g_bsum[(NMAX + SCAN_B - 1) / SCAN_B];
__device__ int    g_csr[EMAX];           // src indices grouped by dst
__device__ float4 g_pool[NG * 16];       // per-graph feature sums
__device__ float  g_cnt[NG];             // per-graph node counts
__device__ int    g_is32;                // 1 if indices are int32 on the wire

// ---------------- helpers ----------------
__device__ __forceinline__ int load_idx(const void* p, long long i, int is32) {
    if (is32) return ((const int*)p)[i];
    return (int)((const long long*)p)[i];
}

__device__ __forceinline__ void red_add_v4(float* addr, float4 v) {
    asm volatile("red.global.add.v4.f32 [%0], {%1,%2,%3,%4};"
                 :: "l"(addr), "f"(v.x), "f"(v.y), "f"(v.z), "f"(v.w)
                 : "memory");
}

// ---------------- kernels ----------------

// Detect index dtype: int64 data has all high words zero; int32 does not.
__global__ void k_detect(const void* __restrict__ ei) {
    if (threadIdx.x == 0) {
        const long long* p = (const long long*)ei;
        int hi_nonzero = 0;
        for (int i = 0; i < 128; i++) {
            long long v = p[i];
            if ((unsigned long long)v > 0xFFFFFFFFull) hi_nonzero = 1;
        }
        g_is32 = hi_nonzero;
    }
}

// deg = 0, pool = 0, cnt = 0
__global__ void k_init(int n) {
    int i = blockIdx.x * blockDim.x + threadIdx.x;
    if (i < n) g_degi[i] = 0;
    if (i < NG * 16) g_pool[i] = make_float4(0.f, 0.f, 0.f, 0.f);
    if (i < NG) g_cnt[i] = 0.0f;
}

// deg[dst] += 1 over edges
__global__ void k_deg(const void* __restrict__ ei, int E) {
    int e = blockIdx.x * blockDim.x + threadIdx.x;
    if (e >= E) return;
    int dst = load_idx(ei, (long long)E + e, g_is32);
    atomicAdd(&g_degi[dst], 1);
}

// per-block exclusive scan of deg; block sums to g_bsum
__global__ void k_scan1(int n) {
    __shared__ int ws[8];
    int i = blockIdx.x * SCAN_B + threadIdx.x;
    int v = (i < n) ? g_degi[i] : 0;
    int lane = threadIdx.x & 31, w = threadIdx.x >> 5;
    int x = v;
#pragma unroll
    for (int o = 1; o < 32; o <<= 1) {
        int y = __shfl_up_sync(~0u, x, o);
        if (lane >= o) x += y;
    }
    if (lane == 31) ws[w] = x;
    __syncthreads();
    if (w == 0) {
        int y = (lane < 8) ? ws[lane] : 0;
#pragma unroll
        for (int o = 1; o < 8; o <<= 1) {
            int z = __shfl_up_sync(~0u, y, o);
            if (lane >= o) y += z;
        }
        if (lane < 8) ws[lane] = y;
    }
    __syncthreads();
    int incl = x + (w > 0 ? ws[w - 1] : 0);
    if (i < n) g_rowtmp[i] = incl - v;
    if (threadIdx.x == SCAN_B - 1) g_bsum[blockIdx.x] = incl;
}

// exclusive scan of block sums (nb <= 256), single block
__global__ void k_scan2(int nb) {
    __shared__ int ws[8];
    int lane = threadIdx.x & 31, w = threadIdx.x >> 5;
    int v = (threadIdx.x < nb) ? g_bsum[threadIdx.x] : 0;
    int x = v;
#pragma unroll
    for (int o = 1; o < 32; o <<= 1) {
        int y = __shfl_up_sync(~0u, x, o);
        if (lane >= o) x += y;
    }
    if (lane == 31) ws[w] = x;
    __syncthreads();
    if (w == 0) {
        int y = (lane < 8) ? ws[lane] : 0;
#pragma unroll
        for (int o = 1; o < 8; o <<= 1) {
            int z = __shfl_up_sync(~0u, y, o);
            if (lane >= o) y += z;
        }
        if (lane < 8) ws[lane] = y;
    }
    __syncthreads();
    int excl = x - v + (w > 0 ? ws[w - 1] : 0);
    if (threadIdx.x < nb) g_bsum[threadIdx.x] = excl;
}

// rowptr = rowtmp + bsum[block]; cursor = rowptr; dis = rsqrt(deg+1)
__global__ void k_scan3(int n) {
    int i = blockIdx.x * SCAN_B + threadIdx.x;
    if (i >= n) return;
    int r = g_rowtmp[i] + g_bsum[blockIdx.x];
    g_rowptr[i] = r;
    g_cursor[i] = r;
    g_dis[i] = rsqrtf((float)(g_degi[i] + 1));
}

// scatter edges into CSR grouped by dst
__global__ void k_fill(const void* __restrict__ ei, int E) {
    int e = blockIdx.x * blockDim.x + threadIdx.x;
    if (e >= E) return;
    int is32 = g_is32;
    int src = load_idx(ei, e, is32);
    int dst = load_idx(ei, (long long)E + e, is32);
    int pos = atomicAdd(&g_cursor[dst], 1);
    g_csr[pos] = src;
}

// ht = (X @ W) * dis[row]; 4 threads per row, 16 output columns each.
__global__ void k_gemm(const float* __restrict__ X, const float* __restrict__ W,
                       float* __restrict__ ht, int n)
{
    __shared__ float4 Ws4[DH * 16];
    const float4* W4 = (const float4*)W;
    for (int i = threadIdx.x; i < DH * 16; i += blockDim.x) Ws4[i] = W4[i];
    __syncthreads();

    int row = blockIdx.x * 64 + (threadIdx.x >> 2);
    int q   = threadIdx.x & 3;
    if (row >= n) return;

    const float4* x4 = (const float4*)(X + (size_t)row * DH);
    float4 acc[4];
#pragma unroll
    for (int j = 0; j < 4; j++) acc[j] = make_float4(0.f, 0.f, 0.f, 0.f);

#pragma unroll
    for (int kk = 0; kk < 16; kk++) {
        float4 xk = x4[kk];
#pragma unroll
        for (int c = 0; c < 4; c++) {
            float xv = (c == 0) ? xk.x : (c == 1) ? xk.y : (c == 2) ? xk.z : xk.w;
            int k = kk * 4 + c;
#pragma unroll
            for (int j = 0; j < 4; j++) {
                float4 w = Ws4[k * 16 + q * 4 + j];
                acc[j].x += xv * w.x;
                acc[j].y += xv * w.y;
                acc[j].z += xv * w.z;
                acc[j].w += xv * w.w;
            }
        }
    }

    float ds = g_dis[row];
    float4* hto = (float4*)(ht + (size_t)row * DH) + q * 4;
#pragma unroll
    for (int j = 0; j < 4; j++)
        hto[j] = make_float4(acc[j].x * ds, acc[j].y * ds,
                             acc[j].z * ds, acc[j].w * ds);
}

// Aggregate: out[dst] = relu( dis[dst] * (ht[dst] + sum_{src} ht[src]) + b )
// 16 lanes per node, one float4 each. POOL adds global-mean-pool atomics.
template<bool POOL>
__global__ void k_agg(const float* __restrict__ ht, const float* __restrict__ b,
                      float* __restrict__ out, const void* __restrict__ batch, int n)
{
    int t = blockIdx.x * blockDim.x + threadIdx.x;
    int node = t >> 4;
    if (node >= n) return;
    int l = t & 15;

    const float4* ht4 = (const float4*)ht;
    float4 acc = ht4[(size_t)node * 16 + l];   // self-loop term

    int k  = g_rowptr[node];
    int e  = k + g_degi[node];

    // 2-way unrolled gather for MLP
    for (; k + 1 < e; k += 2) {
        int s0 = g_csr[k];
        int s1 = g_csr[k + 1];
        float4 v0 = ht4[(size_t)s0 * 16 + l];
        float4 v1 = ht4[(size_t)s1 * 16 + l];
        acc.x += v0.x; acc.y += v0.y; acc.z += v0.z; acc.w += v0.w;
        acc.x += v1.x; acc.y += v1.y; acc.z += v1.z; acc.w += v1.w;
    }
    if (k < e) {
        int s = g_csr[k];
        float4 v = ht4[(size_t)s * 16 + l];
        acc.x += v.x; acc.y += v.y; acc.z += v.z; acc.w += v.w;
    }

    float ds = g_dis[node];
    float4 bb = ((const float4*)b)[l];
    float4 r;
    r.x = fmaxf(acc.x * ds + bb.x, 0.f);
    r.y = fmaxf(acc.y * ds + bb.y, 0.f);
    r.z = fmaxf(acc.z * ds + bb.z, 0.f);
    r.w = fmaxf(acc.w * ds + bb.w, 0.f);

    if (POOL) {
        int gph = load_idx(batch, node, g_is32);
        red_add_v4((float*)g_pool + (size_t)gph * DH + l * 4, r);
        if (l == 0) atomicAdd(&g_cnt[gph], 1.0f);
    } else {
        ((float4*)out)[(size_t)node * 16 + l] = r;
    }
}

// out[g, c] = (pool[g] / max(cnt,1)) @ Wfc + bfc
__global__ void k_fc(const float* __restrict__ Wfc, const float* __restrict__ bfc,
                     float* __restrict__ out)
{
    int t = threadIdx.x;
    if (t >= NG * NCLS) return;
    int gph = t / NCLS, c = t % NCLS;
    float inv = 1.0f / fmaxf(g_cnt[gph], 1.0f);
    const float* pr = (const float*)g_pool + (size_t)gph * DH;
    float acc = 0.f;
#pragma unroll
    for (int j = 0; j < DH; j++) acc += pr[j] * Wfc[j * NCLS + c];
    out[t] = acc * inv + bfc[c];
}

// ---------------- launcher ----------------
extern "C" void kernel_launch(void* const* d_in, const int* in_sizes, int n_in,
                              void* d_out, int out_size)
{
    const float* x   = (const float*)d_in[0];
    const void*  ei  = d_in[1];
    const void*  bat = d_in[2];
    const float* W1  = (const float*)d_in[3];
    const float* b1  = (const float*)d_in[4];
    const float* W2  = (const float*)d_in[5];
    const float* b2  = (const float*)d_in[6];
    const float* Wfc = (const float*)d_in[7];
    const float* bfc = (const float*)d_in[8];
    float* out = (float*)d_out;

    int n = in_sizes[0] / DH;       // nodes
    int E = in_sizes[1] / 2;        // edges

    static float* pA = nullptr; static float* pC = nullptr;
    if (!pA) {
        void* tmp;
        cudaGetSymbolAddress(&tmp, g_A); pA = (float*)tmp;
        cudaGetSymbolAddress(&tmp, g_C); pC = (float*)tmp;
    }

    const int TB = 256;
    int nb_scan = (n + SCAN_B - 1) / SCAN_B;

    k_detect<<<1, 32>>>(ei);
    k_init<<<(n + TB - 1) / TB, TB>>>(n);
    k_deg<<<(E + TB - 1) / TB, TB>>>(ei, E);
    k_scan1<<<nb_scan, SCAN_B>>>(n);
    k_scan2<<<1, SCAN_B>>>(nb_scan);
    k_scan3<<<nb_scan, SCAN_B>>>(n);
    k_fill<<<(E + TB - 1) / TB, TB>>>(ei, E);

    int gemm_blocks = (n + 63) / 64;
    int agg_blocks  = ((long long)n * 16 + TB - 1) / TB;

    // layer 1: ht1 -> A, h1 -> C
    k_gemm<<<gemm_blocks, TB>>>(x, W1, pA, n);
    k_agg<false><<<agg_blocks, TB>>>(pA, b1, pC, nullptr, n);

    // layer 2: ht2 -> A, aggregate + pool
    k_gemm<<<gemm_blocks, TB>>>(pC, W2, pA, n);
    k_agg<true><<<agg_blocks, TB>>>(pA, b2, nullptr, bat, n);

    k_fc<<<1, NG * NCLS>>>(Wfc, bfc, out);
}

// round 3
// speedup vs baseline: 1.4443x; 1.0234x over previous
#include <cuda_runtime.h>
#include <cuda_fp16.h>
#include <cstdint>

// ---------------- problem constants (capacities) ----------------
#define NMAX   50000
#define EMAX   1600000
#define DH     64
#define NG     64
#define NCLS   10
#define SCAN_B 256

// ---------------- device scratch (no allocations allowed) -------
__device__ __half2 g_Ah[NMAX * 32];      // ht buffer, fp16 (row = 128B)
__device__ float4  g_C[NMAX * 16];       // layer-1 activation (fp32)
__device__ float   g_dis[NMAX];          // rsqrt(deg+1)
__device__ int     g_degi[NMAX];         // edge in-degree (no self loop)
__device__ int     g_rowtmp[NMAX];       // per-block exclusive scan
__device__ int     g_rowptr[NMAX];       // CSR row offsets
__device__ int     g_cursor[NMAX];       // fill cursors
__device__ int     g_bsum[(NMAX + SCAN_B - 1) / SCAN_B];
__device__ int     g_csr[EMAX];          // src indices grouped by dst
__device__ float4  g_pool[NG * 16];      // per-graph feature sums
__device__ float   g_cnt[NG];            // per-graph node counts
__device__ int     g_is32;               // 1 if indices are int32 on the wire

// ---------------- helpers ----------------
__device__ __forceinline__ int load_idx(const void* p, long long i, int is32) {
    if (is32) return ((const int*)p)[i];
    return (int)((const long long*)p)[i];
}

__device__ __forceinline__ void red_add_v4(float* addr, float4 v) {
    asm volatile("red.global.add.v4.f32 [%0], {%1,%2,%3,%4};"
                 :: "l"(addr), "f"(v.x), "f"(v.y), "f"(v.z), "f"(v.w)
                 : "memory");
}

__device__ __forceinline__ void acc_u4(float* acc, uint4 u) {
    __half2 h0 = *(__half2*)&u.x, h1 = *(__half2*)&u.y;
    __half2 h2 = *(__half2*)&u.z, h3 = *(__half2*)&u.w;
    float2 f0 = __half22float2(h0), f1 = __half22float2(h1);
    float2 f2 = __half22float2(h2), f3 = __half22float2(h3);
    acc[0] += f0.x; acc[1] += f0.y; acc[2] += f1.x; acc[3] += f1.y;
    acc[4] += f2.x; acc[5] += f2.y; acc[6] += f3.x; acc[7] += f3.y;
}

// ---------------- kernels ----------------

// init scratch; thread 0 of block 0 detects index dtype
__global__ void k_init(const void* __restrict__ ei, int n) {
    int i = blockIdx.x * blockDim.x + threadIdx.x;
    if (i == 0) {
        const long long* p = (const long long*)ei;
        int hi_nonzero = 0;
        for (int j = 0; j < 128; j++)
            if ((unsigned long long)p[j] > 0xFFFFFFFFull) hi_nonzero = 1;
        g_is32 = hi_nonzero;
    }
    if (i < n) g_degi[i] = 0;
    if (i < NG * 16) g_pool[i] = make_float4(0.f, 0.f, 0.f, 0.f);
    if (i < NG) g_cnt[i] = 0.0f;
}

// deg[dst] += 1 over edges
__global__ void k_deg(const void* __restrict__ ei, int E) {
    int e = blockIdx.x * blockDim.x + threadIdx.x;
    if (e >= E) return;
    int dst = load_idx(ei, (long long)E + e, g_is32);
    atomicAdd(&g_degi[dst], 1);
}

// per-block exclusive scan of deg; block sums to g_bsum
__global__ void k_scan1(int n) {
    __shared__ int ws[8];
    int i = blockIdx.x * SCAN_B + threadIdx.x;
    int v = (i < n) ? g_degi[i] : 0;
    int lane = threadIdx.x & 31, w = threadIdx.x >> 5;
    int x = v;
#pragma unroll
    for (int o = 1; o < 32; o <<= 1) {
        int y = __shfl_up_sync(~0u, x, o);
        if (lane >= o) x += y;
    }
    if (lane == 31) ws[w] = x;
    __syncthreads();
    if (w == 0) {
        int y = (lane < 8) ? ws[lane] : 0;
#pragma unroll
        for (int o = 1; o < 8; o <<= 1) {
            int z = __shfl_up_sync(~0u, y, o);
            if (lane >= o) y += z;
        }
        if (lane < 8) ws[lane] = y;
    }
    __syncthreads();
    int incl = x + (w > 0 ? ws[w - 1] : 0);
    if (i < n) g_rowtmp[i] = incl - v;
    if (threadIdx.x == SCAN_B - 1) g_bsum[blockIdx.x] = incl;
}

// exclusive scan of block sums (nb <= 256), single block
__global__ void k_scan2(int nb) {
    __shared__ int ws[8];
    int lane = threadIdx.x & 31, w = threadIdx.x >> 5;
    int v = (threadIdx.x < nb) ? g_bsum[threadIdx.x] : 0;
    int x = v;
#pragma unroll
    for (int o = 1; o < 32; o <<= 1) {
        int y = __shfl_up_sync(~0u, x, o);
        if (lane >= o) x += y;
    }
    if (lane == 31) ws[w] = x;
    __syncthreads();
    if (w == 0) {
        int y = (lane < 8) ? ws[lane] : 0;
#pragma unroll
        for (int o = 1; o < 8; o <<= 1) {
            int z = __shfl_up_sync(~0u, y, o);
            if (lane >= o) y += z;
        }
        if (lane < 8) ws[lane] = y;
    }
    __syncthreads();
    int excl = x - v + (w > 0 ? ws[w - 1] : 0);
    if (threadIdx.x < nb) g_bsum[threadIdx.x] = excl;
}

// rowptr = rowtmp + bsum[block]; cursor = rowptr; dis = rsqrt(deg+1)
__global__ void k_scan3(int n) {
    int i = blockIdx.x * SCAN_B + threadIdx.x;
    if (i >= n) return;
    int r = g_rowtmp[i] + g_bsum[blockIdx.x];
    g_rowptr[i] = r;
    g_cursor[i] = r;
    g_dis[i] = rsqrtf((float)(g_degi[i] + 1));
}

// scatter edges into CSR grouped by dst
__global__ void k_fill(const void* __restrict__ ei, int E) {
    int e = blockIdx.x * blockDim.x + threadIdx.x;
    if (e >= E) return;
    int is32 = g_is32;
    int src = load_idx(ei, e, is32);
    int dst = load_idx(ei, (long long)E + e, is32);
    int pos = atomicAdd(&g_cursor[dst], 1);
    g_csr[pos] = src;
}

// ht_half = (X @ W) * dis[row]; 4 threads per row, 16 output columns each.
__global__ void k_gemm(const float* __restrict__ X, const float* __restrict__ W,
                       __half2* __restrict__ ht, int n)
{
    __shared__ float4 Ws4[DH * 16];
    const float4* W4 = (const float4*)W;
    for (int i = threadIdx.x; i < DH * 16; i += blockDim.x) Ws4[i] = W4[i];
    __syncthreads();

    int row = blockIdx.x * 64 + (threadIdx.x >> 2);
    int q   = threadIdx.x & 3;
    if (row >= n) return;

    const float4* x4 = (const float4*)(X + (size_t)row * DH);
    float4 acc[4];
#pragma unroll
    for (int j = 0; j < 4; j++) acc[j] = make_float4(0.f, 0.f, 0.f, 0.f);

#pragma unroll
    for (int kk = 0; kk < 16; kk++) {
        float4 xk = x4[kk];
#pragma unroll
        for (int c = 0; c < 4; c++) {
            float xv = (c == 0) ? xk.x : (c == 1) ? xk.y : (c == 2) ? xk.z : xk.w;
            int k = kk * 4 + c;
#pragma unroll
            for (int j = 0; j < 4; j++) {
                float4 w = Ws4[k * 16 + q * 4 + j];
                acc[j].x += xv * w.x;
                acc[j].y += xv * w.y;
                acc[j].z += xv * w.z;
                acc[j].w += xv * w.w;
            }
        }
    }

    float ds = g_dis[row];
    // thread writes 16 cols = 8 half2 = two uint4 stores
    uint4 o0, o1;
    __half2* ph = (__half2*)&o0;
#pragma unroll
    for (int j = 0; j < 2; j++) {
        float2 p0 = make_float2(acc[j].x * ds, acc[j].y * ds);
        float2 p1 = make_float2(acc[j].z * ds, acc[j].w * ds);
        ph[j * 2 + 0] = __float22half2_rn(p0);
        ph[j * 2 + 1] = __float22half2_rn(p1);
    }
    __half2* qh = (__half2*)&o1;
#pragma unroll
    for (int j = 0; j < 2; j++) {
        float2 p0 = make_float2(acc[2 + j].x * ds, acc[2 + j].y * ds);
        float2 p1 = make_float2(acc[2 + j].z * ds, acc[2 + j].w * ds);
        qh[j * 2 + 0] = __float22half2_rn(p0);
        qh[j * 2 + 1] = __float22half2_rn(p1);
    }
    uint4* dst = (uint4*)(ht + (size_t)row * 32) + q * 2;
    dst[0] = o0;
    dst[1] = o1;
}

// Aggregate: out[dst] = relu( dis[dst] * (ht[dst] + sum_{src} ht[src]) + b )
// 8 lanes per node; lane owns 16B (8 halves) of the 128B row.
template<bool POOL>
__global__ void k_agg(const __half2* __restrict__ ht, const float* __restrict__ b,
                      float* __restrict__ out, const void* __restrict__ batch, int n)
{
    int t = blockIdx.x * blockDim.x + threadIdx.x;
    int node = t >> 3;
    if (node >= n) return;
    int l = t & 7;

    const uint4* ht4 = (const uint4*)ht;   // row stride = 8 uint4
    float acc[8];
    {
        uint4 self = ht4[(size_t)node * 8 + l];
#pragma unroll
        for (int j = 0; j < 8; j++) acc[j] = 0.f;
        acc_u4(acc, self);
    }

    int k = g_rowptr[node];
    int e = k + g_degi[node];

    for (; k + 4 <= e; k += 4) {
        int s0 = g_csr[k];
        int s1 = g_csr[k + 1];
        int s2 = g_csr[k + 2];
        int s3 = g_csr[k + 3];
        uint4 v0 = ht4[(size_t)s0 * 8 + l];
        uint4 v1 = ht4[(size_t)s1 * 8 + l];
        uint4 v2 = ht4[(size_t)s2 * 8 + l];
        uint4 v3 = ht4[(size_t)s3 * 8 + l];
        acc_u4(acc, v0);
        acc_u4(acc, v1);
        acc_u4(acc, v2);
        acc_u4(acc, v3);
    }
    for (; k < e; k++) {
        int s = g_csr[k];
        uint4 v = ht4[(size_t)s * 8 + l];
        acc_u4(acc, v);
    }

    float ds = g_dis[node];
    const float4* b4 = (const float4*)b;   // 16 float4s; lane owns 2
    float4 b0 = b4[l * 2], b1 = b4[l * 2 + 1];
    float4 r0, r1;
    r0.x = fmaxf(acc[0] * ds + b0.x, 0.f);
    r0.y = fmaxf(acc[1] * ds + b0.y, 0.f);
    r0.z = fmaxf(acc[2] * ds + b0.z, 0.f);
    r0.w = fmaxf(acc[3] * ds + b0.w, 0.f);
    r1.x = fmaxf(acc[4] * ds + b1.x, 0.f);
    r1.y = fmaxf(acc[5] * ds + b1.y, 0.f);
    r1.z = fmaxf(acc[6] * ds + b1.z, 0.f);
    r1.w = fmaxf(acc[7] * ds + b1.w, 0.f);

    if (POOL) {
        int gph = load_idx(batch, node, g_is32);
        float* pp = (float*)g_pool + (size_t)gph * DH + l * 8;
        red_add_v4(pp, r0);
        red_add_v4(pp + 4, r1);
        if (l == 0) atomicAdd(&g_cnt[gph], 1.0f);
    } else {
        float4* o = (float4*)(out + (size_t)node * DH) + l * 2;
        o[0] = r0;
        o[1] = r1;
    }
}

// out[g, c] = (pool[g] / max(cnt,1)) @ Wfc + bfc
__global__ void k_fc(const float* __restrict__ Wfc, const float* __restrict__ bfc,
                     float* __restrict__ out)
{
    int t = threadIdx.x;
    if (t >= NG * NCLS) return;
    int gph = t / NCLS, c = t % NCLS;
    float inv = 1.0f / fmaxf(g_cnt[gph], 1.0f);
    const float* pr = (const float*)g_pool + (size_t)gph * DH;
    float acc = 0.f;
#pragma unroll
    for (int j = 0; j < DH; j++) acc += pr[j] * Wfc[j * NCLS + c];
    out[t] = acc * inv + bfc[c];
}

// ---------------- launcher ----------------
extern "C" void kernel_launch(void* const* d_in, const int* in_sizes, int n_in,
                              void* d_out, int out_size)
{
    const float* x   = (const float*)d_in[0];
    const void*  ei  = d_in[1];
    const void*  bat = d_in[2];
    const float* W1  = (const float*)d_in[3];
    const float* b1  = (const float*)d_in[4];
    const float* W2  = (const float*)d_in[5];
    const float* b2  = (const float*)d_in[6];
    const float* Wfc = (const float*)d_in[7];
    const float* bfc = (const float*)d_in[8];
    float* out = (float*)d_out;

    int n = in_sizes[0] / DH;       // nodes
    int E = in_sizes[1] / 2;        // edges

    static __half2* pA = nullptr; static float* pC = nullptr;
    if (!pA) {
        void* tmp;
        cudaGetSymbolAddress(&tmp, g_Ah); pA = (__half2*)tmp;
        cudaGetSymbolAddress(&tmp, g_C);  pC = (float*)tmp;
    }

    const int TB = 256;
    int nb_scan = (n + SCAN_B - 1) / SCAN_B;

    k_init<<<(n + TB - 1) / TB, TB>>>(ei, n);
    k_deg<<<(E + TB - 1) / TB, TB>>>(ei, E);
    k_scan1<<<nb_scan, SCAN_B>>>(n);
    k_scan2<<<1, SCAN_B>>>(nb_scan);
    k_scan3<<<nb_scan, SCAN_B>>>(n);
    k_fill<<<(E + TB - 1) / TB, TB>>>(ei, E);

    int gemm_blocks = (n + 63) / 64;
    int agg_blocks  = ((long long)n * 8 + TB - 1) / TB;

    // layer 1: ht1 -> Ah, h1 -> C
    k_gemm<<<gemm_blocks, TB>>>(x, W1, pA, n);
    k_agg<false><<<agg_blocks, TB>>>(pA, b1, pC, nullptr, n);

    // layer 2: ht2 -> Ah, aggregate + pool
    k_gemm<<<gemm_blocks, TB>>>(pC, W2, pA, n);
    k_agg<true><<<agg_blocks, TB>>>(pA, b2, nullptr, bat, n);

    k_fc<<<1, NG * NCLS>>>(Wfc, bfc, out);
}

// round 4
// speedup vs baseline: 1.7623x; 1.2202x over previous
#include <cuda_runtime.h>
#include <cuda_fp16.h>
#include <cstdint>

// ---------------- problem constants (capacities) ----------------
#define NMAX   50000
#define EMAX   1600000
#define DH     64
#define NG     64
#define NCLS   10
#define SCAN_B 256

// ---------------- device scratch (no allocations allowed) -------
__device__ __half2 g_Ah1[NMAX * 32];     // ht1 table, fp16 (row = 128B)
__device__ __half2 g_Ah2[NMAX * 32];     // ht2 table, fp16
__device__ float   g_dis[NMAX];          // rsqrt(deg+1)
__device__ int     g_degi[NMAX];         // edge in-degree (no self loop)
__device__ int     g_rowtmp[NMAX];       // per-block exclusive scan
__device__ int     g_cnt2[NMAX];         // fill cursors (offset within row)
__device__ int     g_bsum[(NMAX + SCAN_B - 1) / SCAN_B];
__device__ int     g_csr[EMAX];          // src indices grouped by dst
__device__ float4  g_pool[NG * 16];      // per-graph feature sums
__device__ float   g_cnt[NG];            // per-graph node counts
__device__ int     g_is32;               // 1 if indices are int32 on the wire

// ---------------- helpers ----------------
__device__ __forceinline__ int load_idx(const void* p, long long i, int is32) {
    if (is32) return ((const int*)p)[i];
    return (int)((const long long*)p)[i];
}

__device__ __forceinline__ void red_add_v4(float* addr, float4 v) {
    asm volatile("red.global.add.v4.f32 [%0], {%1,%2,%3,%4};"
                 :: "l"(addr), "f"(v.x), "f"(v.y), "f"(v.z), "f"(v.w)
                 : "memory");
}

__device__ __forceinline__ void acc_u4(float* acc, uint4 u) {
    __half2 h0 = *(__half2*)&u.x, h1 = *(__half2*)&u.y;
    __half2 h2 = *(__half2*)&u.z, h3 = *(__half2*)&u.w;
    float2 f0 = __half22float2(h0), f1 = __half22float2(h1);
    float2 f2 = __half22float2(h2), f3 = __half22float2(h3);
    acc[0] += f0.x; acc[1] += f0.y; acc[2] += f1.x; acc[3] += f1.y;
    acc[4] += f2.x; acc[5] += f2.y; acc[6] += f3.x; acc[7] += f3.y;
}

// virtual rowptr
__device__ __forceinline__ int rowptr_of(int i) {
    return g_rowtmp[i] + g_bsum[i >> 8];
}

// ---------------- kernels ----------------

// init scratch; thread 0 detects index dtype
__global__ void k_init(const void* __restrict__ ei, int n) {
    int i = blockIdx.x * blockDim.x + threadIdx.x;
    if (i == 0) {
        const long long* p = (const long long*)ei;
        int hi_nonzero = 0;
        for (int j = 0; j < 128; j++)
            if ((unsigned long long)p[j] > 0xFFFFFFFFull) hi_nonzero = 1;
        g_is32 = hi_nonzero;
    }
    if (i < n) { g_degi[i] = 0; g_cnt2[i] = 0; }
    if (i < NG * 16) g_pool[i] = make_float4(0.f, 0.f, 0.f, 0.f);
    if (i < NG) g_cnt[i] = 0.0f;
}

// deg[dst] += 1 over edges, 2 edges per thread
__global__ void k_deg(const void* __restrict__ ei, int E) {
    int t = blockIdx.x * blockDim.x + threadIdx.x;
    int e = t * 2;
    if (e >= E) return;
    if (g_is32) {
        const int* dstp = (const int*)ei + E;
        if (e + 1 < E) {
            int2 d = ((const int2*)dstp)[t];
            atomicAdd(&g_degi[d.x], 1);
            atomicAdd(&g_degi[d.y], 1);
        } else {
            atomicAdd(&g_degi[dstp[e]], 1);
        }
    } else {
        const long long* dstp = (const long long*)ei + E;
        if (e + 1 < E) {
            longlong2 d = ((const longlong2*)dstp)[t];
            atomicAdd(&g_degi[(int)d.x], 1);
            atomicAdd(&g_degi[(int)d.y], 1);
        } else {
            atomicAdd(&g_degi[(int)dstp[e]], 1);
        }
    }
}

// per-block exclusive scan of deg; block sums to g_bsum; dis = rsqrt(deg+1)
__global__ void k_scan1(int n) {
    __shared__ int ws[8];
    int i = blockIdx.x * SCAN_B + threadIdx.x;
    int v = (i < n) ? g_degi[i] : 0;
    int lane = threadIdx.x & 31, w = threadIdx.x >> 5;
    int x = v;
#pragma unroll
    for (int o = 1; o < 32; o <<= 1) {
        int y = __shfl_up_sync(~0u, x, o);
        if (lane >= o) x += y;
    }
    if (lane == 31) ws[w] = x;
    __syncthreads();
    if (w == 0) {
        int y = (lane < 8) ? ws[lane] : 0;
#pragma unroll
        for (int o = 1; o < 8; o <<= 1) {
            int z = __shfl_up_sync(~0u, y, o);
            if (lane >= o) y += z;
        }
        if (lane < 8) ws[lane] = y;
    }
    __syncthreads();
    int incl = x + (w > 0 ? ws[w - 1] : 0);
    if (i < n) {
        g_rowtmp[i] = incl - v;
        g_dis[i] = rsqrtf((float)(v + 1));
    }
    if (threadIdx.x == SCAN_B - 1) g_bsum[blockIdx.x] = incl;
}

// block 0: exclusive scan of block sums (nb <= 256).
// blocks >= 1: gemm1: ht1 = (X @ W1) * dis[row], fp16 out.
__global__ void k_scan2_gemm1(int nb, const float* __restrict__ X,
                              const float* __restrict__ W,
                              __half2* __restrict__ ht, int n)
{
    if (blockIdx.x == 0) {
        __shared__ int ws[8];
        int lane = threadIdx.x & 31, w = threadIdx.x >> 5;
        int v = (threadIdx.x < nb) ? g_bsum[threadIdx.x] : 0;
        int x = v;
#pragma unroll
        for (int o = 1; o < 32; o <<= 1) {
            int y = __shfl_up_sync(~0u, x, o);
            if (lane >= o) x += y;
        }
        if (lane == 31) ws[w] = x;
        __syncthreads();
        if (w == 0) {
            int y = (lane < 8) ? ws[lane] : 0;
#pragma unroll
            for (int o = 1; o < 8; o <<= 1) {
                int z = __shfl_up_sync(~0u, y, o);
                if (lane >= o) y += z;
            }
            if (lane < 8) ws[lane] = y;
        }
        __syncthreads();
        int excl = x - v + (w > 0 ? ws[w - 1] : 0);
        if (threadIdx.x < nb) g_bsum[threadIdx.x] = excl;
        return;
    }

    // ---- gemm part ----
    __shared__ float4 Ws4[DH * 16];
    const float4* W4 = (const float4*)W;
    for (int i = threadIdx.x; i < DH * 16; i += blockDim.x) Ws4[i] = W4[i];
    __syncthreads();

    int row = (blockIdx.x - 1) * 64 + (threadIdx.x >> 2);
    int q   = threadIdx.x & 3;
    if (row >= n) return;

    const float4* x4 = (const float4*)(X + (size_t)row * DH);
    float4 acc[4];
#pragma unroll
    for (int j = 0; j < 4; j++) acc[j] = make_float4(0.f, 0.f, 0.f, 0.f);

#pragma unroll
    for (int kk = 0; kk < 16; kk++) {
        float4 xk = x4[kk];
#pragma unroll
        for (int c = 0; c < 4; c++) {
            float xv = (c == 0) ? xk.x : (c == 1) ? xk.y : (c == 2) ? xk.z : xk.w;
            int k = kk * 4 + c;
#pragma unroll
            for (int j = 0; j < 4; j++) {
                float4 w = Ws4[k * 16 + q * 4 + j];
                acc[j].x += xv * w.x;
                acc[j].y += xv * w.y;
                acc[j].z += xv * w.z;
                acc[j].w += xv * w.w;
            }
        }
    }

    float ds = g_dis[row];
    uint4 o0, o1;
    __half2* ph = (__half2*)&o0;
#pragma unroll
    for (int j = 0; j < 2; j++) {
        ph[j * 2 + 0] = __floats2half2_rn(acc[j].x * ds, acc[j].y * ds);
        ph[j * 2 + 1] = __floats2half2_rn(acc[j].z * ds, acc[j].w * ds);
    }
    __half2* qh = (__half2*)&o1;
#pragma unroll
    for (int j = 0; j < 2; j++) {
        qh[j * 2 + 0] = __floats2half2_rn(acc[2 + j].x * ds, acc[2 + j].y * ds);
        qh[j * 2 + 1] = __floats2half2_rn(acc[2 + j].z * ds, acc[2 + j].w * ds);
    }
    uint4* dst = (uint4*)(ht + (size_t)row * 32) + q * 2;
    dst[0] = o0;
    dst[1] = o1;
}

// scatter edges into CSR grouped by dst, 2 edges per thread
__global__ void k_fill(const void* __restrict__ ei, int E) {
    int t = blockIdx.x * blockDim.x + threadIdx.x;
    int e = t * 2;
    if (e >= E) return;
    int s0, s1 = -1, d0, d1 = -1;
    if (g_is32) {
        const int* srcp = (const int*)ei;
        const int* dstp = srcp + E;
        if (e + 1 < E) {
            int2 s = ((const int2*)srcp)[t];
            int2 d = ((const int2*)dstp)[t];
            s0 = s.x; s1 = s.y; d0 = d.x; d1 = d.y;
        } else { s0 = srcp[e]; d0 = dstp[e]; }
    } else {
        const long long* srcp = (const long long*)ei;
        const long long* dstp = srcp + E;
        if (e + 1 < E) {
            longlong2 s = ((const longlong2*)srcp)[t];
            longlong2 d = ((const longlong2*)dstp)[t];
            s0 = (int)s.x; s1 = (int)s.y; d0 = (int)d.x; d1 = (int)d.y;
        } else { s0 = (int)srcp[e]; d0 = (int)dstp[e]; }
    }
    int p0 = rowptr_of(d0) + atomicAdd(&g_cnt2[d0], 1);
    g_csr[p0] = s0;
    if (s1 >= 0 || d1 >= 0) {
        int p1 = rowptr_of(d1) + atomicAdd(&g_cnt2[d1], 1);
        g_csr[p1] = s1;
    }
}

// Fused: agg over ht1 -> h1 (smem) -> gemv W2 -> ht2 (fp16, pre-scaled by dis)
// Block: 32 nodes, 256 threads. Agg phase: 8 lanes/node. Gemv: 2 nodes x 4 cols/thread.
__global__ void k_agg1_gemm2(const __half2* __restrict__ ht1,
                             const float* __restrict__ b,
                             const float* __restrict__ W2,
                             __half2* __restrict__ ht2, int n)
{
    __shared__ float4 W2s[DH * 16];     // 16KB
    __shared__ float4 h1s[32 * 16];     // 8KB: 32 nodes x 64 floats

    const float4* w4 = (const float4*)W2;
    for (int i = threadIdx.x; i < DH * 16; i += blockDim.x) W2s[i] = w4[i];

    int node_l = threadIdx.x >> 3;
    int node = blockIdx.x * 32 + node_l;
    int l = threadIdx.x & 7;

    if (node < n) {
        const uint4* t4 = (const uint4*)ht1;
        float acc[8];
#pragma unroll
        for (int j = 0; j < 8; j++) acc[j] = 0.f;
        acc_u4(acc, t4[(size_t)node * 8 + l]);   // self loop

        int k = rowptr_of(node);
        int e = k + g_degi[node];
        for (; k + 4 <= e; k += 4) {
            int s0 = g_csr[k], s1 = g_csr[k + 1];
            int s2 = g_csr[k + 2], s3 = g_csr[k + 3];
            uint4 v0 = t4[(size_t)s0 * 8 + l];
            uint4 v1 = t4[(size_t)s1 * 8 + l];
            uint4 v2 = t4[(size_t)s2 * 8 + l];
            uint4 v3 = t4[(size_t)s3 * 8 + l];
            acc_u4(acc, v0); acc_u4(acc, v1); acc_u4(acc, v2); acc_u4(acc, v3);
        }
        for (; k < e; k++) acc_u4(acc, t4[(size_t)g_csr[k] * 8 + l]);

        float ds = g_dis[node];
        const float4* b4 = (const float4*)b;
        float4 b0 = b4[l * 2], b1 = b4[l * 2 + 1];
        float4 r0, r1;
        r0.x = fmaxf(acc[0] * ds + b0.x, 0.f);
        r0.y = fmaxf(acc[1] * ds + b0.y, 0.f);
        r0.z = fmaxf(acc[2] * ds + b0.z, 0.f);
        r0.w = fmaxf(acc[3] * ds + b0.w, 0.f);
        r1.x = fmaxf(acc[4] * ds + b1.x, 0.f);
        r1.y = fmaxf(acc[5] * ds + b1.y, 0.f);
        r1.z = fmaxf(acc[6] * ds + b1.z, 0.f);
        r1.w = fmaxf(acc[7] * ds + b1.w, 0.f);
        h1s[node_l * 16 + l * 2]     = r0;
        h1s[node_l * 16 + l * 2 + 1] = r1;
    } else {
        h1s[node_l * 16 + l * 2]     = make_float4(0.f, 0.f, 0.f, 0.f);
        h1s[node_l * 16 + l * 2 + 1] = make_float4(0.f, 0.f, 0.f, 0.f);
    }
    __syncthreads();

    // ---- gemv: ht2[node] = (h1[node] @ W2) * dis[node] ----
    int np = threadIdx.x >> 4;          // 0..15 -> node pair
    int cg = threadIdx.x & 15;          // 0..15 -> 4 cols
    int n0 = np * 2, n1 = np * 2 + 1;
    float4 a0 = make_float4(0.f, 0.f, 0.f, 0.f);
    float4 a1 = make_float4(0.f, 0.f, 0.f, 0.f);

#pragma unroll
    for (int kk = 0; kk < 16; kk++) {
        float4 x0 = h1s[n0 * 16 + kk];
        float4 x1 = h1s[n1 * 16 + kk];
#pragma unroll
        for (int c = 0; c < 4; c++) {
            float4 w = W2s[(kk * 4 + c) * 16 + cg];
            float xv0 = (c == 0) ? x0.x : (c == 1) ? x0.y : (c == 2) ? x0.z : x0.w;
            float xv1 = (c == 0) ? x1.x : (c == 1) ? x1.y : (c == 2) ? x1.z : x1.w;
            a0.x += xv0 * w.x; a0.y += xv0 * w.y; a0.z += xv0 * w.z; a0.w += xv0 * w.w;
            a1.x += xv1 * w.x; a1.y += xv1 * w.y; a1.z += xv1 * w.z; a1.w += xv1 * w.w;
        }
    }

    int gn0 = blockIdx.x * 32 + n0;
    int gn1 = blockIdx.x * 32 + n1;
    if (gn0 < n) {
        float ds = g_dis[gn0];
        uint2 u;
        *(__half2*)&u.x = __floats2half2_rn(a0.x * ds, a0.y * ds);
        *(__half2*)&u.y = __floats2half2_rn(a0.z * ds, a0.w * ds);
        ((uint2*)((__half*)ht2 + (size_t)gn0 * DH))[cg] = u;
    }
    if (gn1 < n) {
        float ds = g_dis[gn1];
        uint2 u;
        *(__half2*)&u.x = __floats2half2_rn(a1.x * ds, a1.y * ds);
        *(__half2*)&u.y = __floats2half2_rn(a1.z * ds, a1.w * ds);
        ((uint2*)((__half*)ht2 + (size_t)gn1 * DH))[cg] = u;
    }
}

// Aggregate layer 2 + global mean pool atomics. 8 lanes/node.
__global__ void k_agg_pool(const __half2* __restrict__ ht,
                           const float* __restrict__ b,
                           const void* __restrict__ batch, int n)
{
    int t = blockIdx.x * blockDim.x + threadIdx.x;
    int node = t >> 3;
    if (node >= n) return;
    int l = t & 7;

    const uint4* t4 = (const uint4*)ht;
    float acc[8];
#pragma unroll
    for (int j = 0; j < 8; j++) acc[j] = 0.f;
    acc_u4(acc, t4[(size_t)node * 8 + l]);

    int k = rowptr_of(node);
    int e = k + g_degi[node];
    for (; k + 4 <= e; k += 4) {
        int s0 = g_csr[k], s1 = g_csr[k + 1];
        int s2 = g_csr[k + 2], s3 = g_csr[k + 3];
        uint4 v0 = t4[(size_t)s0 * 8 + l];
        uint4 v1 = t4[(size_t)s1 * 8 + l];
        uint4 v2 = t4[(size_t)s2 * 8 + l];
        uint4 v3 = t4[(size_t)s3 * 8 + l];
        acc_u4(acc, v0); acc_u4(acc, v1); acc_u4(acc, v2); acc_u4(acc, v3);
    }
    for (; k < e; k++) acc_u4(acc, t4[(size_t)g_csr[k] * 8 + l]);

    float ds = g_dis[node];
    const float4* b4 = (const float4*)b;
    float4 b0 = b4[l * 2], b1 = b4[l * 2 + 1];
    float4 r0, r1;
    r0.x = fmaxf(acc[0] * ds + b0.x, 0.f);
    r0.y = fmaxf(acc[1] * ds + b0.y, 0.f);
    r0.z = fmaxf(acc[2] * ds + b0.z, 0.f);
    r0.w = fmaxf(acc[3] * ds + b0.w, 0.f);
    r1.x = fmaxf(acc[4] * ds + b1.x, 0.f);
    r1.y = fmaxf(acc[5] * ds + b1.y, 0.f);
    r1.z = fmaxf(acc[6] * ds + b1.z, 0.f);
    r1.w = fmaxf(acc[7] * ds + b1.w, 0.f);

    int gph = load_idx(batch, node, g_is32);
    float* pp = (float*)g_pool + (size_t)gph * DH + l * 8;
    red_add_v4(pp, r0);
    red_add_v4(pp + 4, r1);
    if (l == 0) atomicAdd(&g_cnt[gph], 1.0f);
}

// out[g, c] = (pool[g] / max(cnt,1)) @ Wfc + bfc
__global__ void k_fc(const float* __restrict__ Wfc, const float* __restrict__ bfc,
                     float* __restrict__ out)
{
    int t = threadIdx.x;
    if (t >= NG * NCLS) return;
    int gph = t / NCLS, c = t % NCLS;
    float inv = 1.0f / fmaxf(g_cnt[gph], 1.0f);
    const float* pr = (const float*)g_pool + (size_t)gph * DH;
    float acc = 0.f;
#pragma unroll
    for (int j = 0; j < DH; j++) acc += pr[j] * Wfc[j * NCLS + c];
    out[t] = acc * inv + bfc[c];
}

// ---------------- launcher ----------------
extern "C" void kernel_launch(void* const* d_in, const int* in_sizes, int n_in,
                              void* d_out, int out_size)
{
    const float* x   = (const float*)d_in[0];
    const void*  ei  = d_in[1];
    const void*  bat = d_in[2];
    const float* W1  = (const float*)d_in[3];
    const float* b1  = (const float*)d_in[4];
    const float* W2  = (const float*)d_in[5];
    const float* b2  = (const float*)d_in[6];
    const float* Wfc = (const float*)d_in[7];
    const float* bfc = (const float*)d_in[8];
    float* out = (float*)d_out;

    int n = in_sizes[0] / DH;       // nodes
    int E = in_sizes[1] / 2;        // edges

    static __half2* pA1 = nullptr; static __half2* pA2 = nullptr;
    if (!pA1) {
        void* tmp;
        cudaGetSymbolAddress(&tmp, g_Ah1); pA1 = (__half2*)tmp;
        cudaGetSymbolAddress(&tmp, g_Ah2); pA2 = (__half2*)tmp;
    }

    const int TB = 256;
    int nb_scan = (n + SCAN_B - 1) / SCAN_B;
    int half_e_blocks = ((E + 1) / 2 + TB - 1) / TB;
    int gemm_blocks = (n + 63) / 64;
    int fused_blocks = (n + 31) / 32;
    int agg_blocks = ((long long)n * 8 + TB - 1) / TB;

    k_init<<<(n + TB - 1) / TB, TB>>>(ei, n);                       // 1
    k_deg<<<half_e_blocks, TB>>>(ei, E);                            // 2
    k_scan1<<<nb_scan, SCAN_B>>>(n);                                // 3
    k_scan2_gemm1<<<1 + gemm_blocks, TB>>>(nb_scan, x, W1, pA1, n); // 4 (profiled)
    k_fill<<<half_e_blocks, TB>>>(ei, E);                           // 5
    k_agg1_gemm2<<<fused_blocks, TB>>>(pA1, b1, W2, pA2, n);        // 6
    k_agg_pool<<<agg_blocks, TB>>>(pA2, b2, bat, n);                // 7
    k_fc<<<1, NG * NCLS>>>(Wfc, bfc, out);                          // 8
}

// round 5
// speedup vs baseline: 2.1259x; 1.2063x over previous
#include <cuda_runtime.h>
#include <cuda_fp16.h>
#include <cstdint>

// ---------------- problem constants (capacities) ----------------
#define NMAX   50000
#define EMAX   1600000
#define DH     64
#define NG     64
#define NCLS   10
#define SCAN_B 256

// ---------------- device scratch (no allocations allowed) -------
__device__ __half2 g_Ah1[NMAX * 32];     // ht1 table, fp16 (row = 128B)
__device__ __half2 g_Ah2[NMAX * 32];     // ht2 table, fp16
__device__ float   g_dis[NMAX];          // rsqrt(deg+1)
__device__ int     g_degi[NMAX];         // edge in-degree (no self loop)
__device__ int     g_rowtmp[NMAX];       // per-block exclusive scan
__device__ int     g_cnt2[NMAX];         // fill cursors (offset within row)
__device__ int     g_bsum[(NMAX + SCAN_B - 1) / SCAN_B];
__device__ int     g_csr[EMAX];          // src indices grouped by dst
__device__ float4  g_pool[NG * 16];      // per-graph feature sums
__device__ float   g_cnt[NG];            // per-graph node counts
__device__ int     g_is32;               // 1 if indices are int32 on the wire

// ---------------- helpers ----------------
__device__ __forceinline__ int load_idx(const void* p, long long i, int is32) {
    if (is32) return ((const int*)p)[i];
    return (int)((const long long*)p)[i];
}

__device__ __forceinline__ void red_add_v4(float* addr, float4 v) {
    asm volatile("red.global.add.v4.f32 [%0], {%1,%2,%3,%4};"
                 :: "l"(addr), "f"(v.x), "f"(v.y), "f"(v.z), "f"(v.w)
                 : "memory");
}

__device__ __forceinline__ void acc_u4(float* acc, uint4 u) {
    __half2 h0 = *(__half2*)&u.x, h1 = *(__half2*)&u.y;
    __half2 h2 = *(__half2*)&u.z, h3 = *(__half2*)&u.w;
    float2 f0 = __half22float2(h0), f1 = __half22float2(h1);
    float2 f2 = __half22float2(h2), f3 = __half22float2(h3);
    acc[0] += f0.x; acc[1] += f0.y; acc[2] += f1.x; acc[3] += f1.y;
    acc[4] += f2.x; acc[5] += f2.y; acc[6] += f3.x; acc[7] += f3.y;
}

// virtual rowptr
__device__ __forceinline__ int rowptr_of(int i) {
    return g_rowtmp[i] + g_bsum[i >> 8];
}

// pack 8 floats (scaled by ds) into a uint4 of halves
__device__ __forceinline__ uint4 pack8h(const float* v, float ds) {
    uint4 u;
    ((__half2*)&u)[0] = __floats2half2_rn(v[0] * ds, v[1] * ds);
    ((__half2*)&u)[1] = __floats2half2_rn(v[2] * ds, v[3] * ds);
    ((__half2*)&u)[2] = __floats2half2_rn(v[4] * ds, v[5] * ds);
    ((__half2*)&u)[3] = __floats2half2_rn(v[6] * ds, v[7] * ds);
    return u;
}

// ---------------- kernels ----------------

// init scratch; thread 0 detects index dtype
__global__ void k_init(const void* __restrict__ ei, int n) {
    int i = blockIdx.x * blockDim.x + threadIdx.x;
    if (i == 0) {
        const long long* p = (const long long*)ei;
        int hi_nonzero = 0;
        for (int j = 0; j < 128; j++)
            if ((unsigned long long)p[j] > 0xFFFFFFFFull) hi_nonzero = 1;
        g_is32 = hi_nonzero;
    }
    if (i < n) { g_degi[i] = 0; g_cnt2[i] = 0; }
    if (i < NG * 16) g_pool[i] = make_float4(0.f, 0.f, 0.f, 0.f);
    if (i < NG) g_cnt[i] = 0.0f;
}

// deg[dst] += 1 over edges, 2 edges per thread
__global__ void k_deg(const void* __restrict__ ei, int E) {
    int t = blockIdx.x * blockDim.x + threadIdx.x;
    int e = t * 2;
    if (e >= E) return;
    if (g_is32) {
        const int* dstp = (const int*)ei + E;
        if (e + 1 < E) {
            int2 d = ((const int2*)dstp)[t];
            atomicAdd(&g_degi[d.x], 1);
            atomicAdd(&g_degi[d.y], 1);
        } else {
            atomicAdd(&g_degi[dstp[e]], 1);
        }
    } else {
        const long long* dstp = (const long long*)ei + E;
        if (e + 1 < E) {
            longlong2 d = ((const longlong2*)dstp)[t];
            atomicAdd(&g_degi[(int)d.x], 1);
            atomicAdd(&g_degi[(int)d.y], 1);
        } else {
            atomicAdd(&g_degi[(int)dstp[e]], 1);
        }
    }
}

// per-block exclusive scan of deg; block sums to g_bsum; dis = rsqrt(deg+1)
__global__ void k_scan1(int n) {
    __shared__ int ws[8];
    int i = blockIdx.x * SCAN_B + threadIdx.x;
    int v = (i < n) ? g_degi[i] : 0;
    int lane = threadIdx.x & 31, w = threadIdx.x >> 5;
    int x = v;
#pragma unroll
    for (int o = 1; o < 32; o <<= 1) {
        int y = __shfl_up_sync(~0u, x, o);
        if (lane >= o) x += y;
    }
    if (lane == 31) ws[w] = x;
    __syncthreads();
    if (w == 0) {
        int y = (lane < 8) ? ws[lane] : 0;
#pragma unroll
        for (int o = 1; o < 8; o <<= 1) {
            int z = __shfl_up_sync(~0u, y, o);
            if (lane >= o) y += z;
        }
        if (lane < 8) ws[lane] = y;
    }
    __syncthreads();
    int incl = x + (w > 0 ? ws[w - 1] : 0);
    if (i < n) {
        g_rowtmp[i] = incl - v;
        g_dis[i] = rsqrtf((float)(v + 1));
    }
    if (threadIdx.x == SCAN_B - 1) g_bsum[blockIdx.x] = incl;
}

// block 0: exclusive scan of block sums (nb <= 256).
// blocks >= 1: gemm1: ht1 = (X @ W1) * dis[row], fp16 out.
// 256 threads = 32 groups of 8 lanes; each group owns 4 rows.
// Lane l holds x[r][8l..8l+7] in registers; k-broadcast via shfl(width=8).
__global__ void k_scan2_gemm1(int nb, const float* __restrict__ X,
                              const float* __restrict__ W,
                              __half2* __restrict__ ht, int n)
{
    if (blockIdx.x == 0) {
        __shared__ int ws[8];
        int lane = threadIdx.x & 31, w = threadIdx.x >> 5;
        int v = (threadIdx.x < nb) ? g_bsum[threadIdx.x] : 0;
        int x = v;
#pragma unroll
        for (int o = 1; o < 32; o <<= 1) {
            int y = __shfl_up_sync(~0u, x, o);
            if (lane >= o) x += y;
        }
        if (lane == 31) ws[w] = x;
        __syncthreads();
        if (w == 0) {
            int y = (lane < 8) ? ws[lane] : 0;
#pragma unroll
            for (int o = 1; o < 8; o <<= 1) {
                int z = __shfl_up_sync(~0u, y, o);
                if (lane >= o) y += z;
            }
            if (lane < 8) ws[lane] = y;
        }
        __syncthreads();
        int excl = x - v + (w > 0 ? ws[w - 1] : 0);
        if (threadIdx.x < nb) g_bsum[threadIdx.x] = excl;
        return;
    }

    // ---- gemm part ----
    __shared__ float4 Ws4[DH * 16];          // W[64][64] fp32
    const float4* W4 = (const float4*)W;
    for (int i = threadIdx.x; i < DH * 16; i += blockDim.x) Ws4[i] = W4[i];
    __syncthreads();

    int grp = threadIdx.x >> 3;              // 0..31
    int l   = threadIdx.x & 7;               // lane within group
    int r0  = (blockIdx.x - 1) * 128 + grp * 4;

    float xr[4][8];
    float acc[4][8];
#pragma unroll
    for (int r = 0; r < 4; r++)
#pragma unroll
        for (int c = 0; c < 8; c++) { acc[r][c] = 0.f; xr[r][c] = 0.f; }

#pragma unroll
    for (int r = 0; r < 4; r++) {
        int row = r0 + r;
        if (row < n) {
            const float4* xp = (const float4*)(X + (size_t)row * DH);
            float4 a = xp[l * 2];
            float4 bq = xp[l * 2 + 1];
            xr[r][0] = a.x;  xr[r][1] = a.y;  xr[r][2] = a.z;  xr[r][3] = a.w;
            xr[r][4] = bq.x; xr[r][5] = bq.y; xr[r][6] = bq.z; xr[r][7] = bq.w;
        }
    }

    for (int kb = 0; kb < 8; kb++) {
#pragma unroll
        for (int j = 0; j < 8; j++) {
            int k = kb * 8 + j;
            float4 w0 = Ws4[k * 16 + l * 2];
            float4 w1 = Ws4[k * 16 + l * 2 + 1];
            float xv0 = __shfl_sync(~0u, xr[0][j], kb, 8);
            float xv1 = __shfl_sync(~0u, xr[1][j], kb, 8);
            float xv2 = __shfl_sync(~0u, xr[2][j], kb, 8);
            float xv3 = __shfl_sync(~0u, xr[3][j], kb, 8);
#pragma unroll
            for (int r = 0; r < 4; r++) {
                float xv = (r == 0) ? xv0 : (r == 1) ? xv1 : (r == 2) ? xv2 : xv3;
                acc[r][0] += xv * w0.x; acc[r][1] += xv * w0.y;
                acc[r][2] += xv * w0.z; acc[r][3] += xv * w0.w;
                acc[r][4] += xv * w1.x; acc[r][5] += xv * w1.y;
                acc[r][6] += xv * w1.z; acc[r][7] += xv * w1.w;
            }
        }
    }

#pragma unroll
    for (int r = 0; r < 4; r++) {
        int row = r0 + r;
        if (row < n) {
            float ds = g_dis[row];
            ((uint4*)((__half*)ht + (size_t)row * DH))[l] = pack8h(acc[r], ds);
        }
    }
}

// scatter edges into CSR grouped by dst, 2 edges per thread
__global__ void k_fill(const void* __restrict__ ei, int E) {
    int t = blockIdx.x * blockDim.x + threadIdx.x;
    int e = t * 2;
    if (e >= E) return;
    int s0, s1 = -1, d0, d1 = -1;
    if (g_is32) {
        const int* srcp = (const int*)ei;
        const int* dstp = srcp + E;
        if (e + 1 < E) {
            int2 s = ((const int2*)srcp)[t];
            int2 d = ((const int2*)dstp)[t];
            s0 = s.x; s1 = s.y; d0 = d.x; d1 = d.y;
        } else { s0 = srcp[e]; d0 = dstp[e]; }
    } else {
        const long long* srcp = (const long long*)ei;
        const long long* dstp = srcp + E;
        if (e + 1 < E) {
            longlong2 s = ((const longlong2*)srcp)[t];
            longlong2 d = ((const longlong2*)dstp)[t];
            s0 = (int)s.x; s1 = (int)s.y; d0 = (int)d.x; d1 = (int)d.y;
        } else { s0 = (int)srcp[e]; d0 = (int)dstp[e]; }
    }
    int p0 = rowptr_of(d0) + atomicAdd(&g_cnt2[d0], 1);
    g_csr[p0] = s0;
    if (s1 >= 0 || d1 >= 0) {
        int p1 = rowptr_of(d1) + atomicAdd(&g_cnt2[d1], 1);
        g_csr[p1] = s1;
    }
}

// Fused: agg over ht1 -> h1 (registers) -> gemv W2 via shfl -> ht2 (fp16).
// Block: 32 nodes, 256 threads, 8 lanes/node; lane l owns cols 8l..8l+7.
__global__ void k_agg1_gemm2(const __half2* __restrict__ ht1,
                             const float* __restrict__ b,
                             const float* __restrict__ W2,
                             __half2* __restrict__ ht2, int n)
{
    __shared__ uint4 W2h[DH * 8];   // W2[64][64] as fp16, 8KB

    // stage W2 -> fp16 smem
    {
        const float4* w4 = (const float4*)W2;
        for (int i = threadIdx.x; i < DH * 8; i += blockDim.x) {
            float4 a = w4[i * 2], c = w4[i * 2 + 1];
            uint4 u;
            ((__half2*)&u)[0] = __floats2half2_rn(a.x, a.y);
            ((__half2*)&u)[1] = __floats2half2_rn(a.z, a.w);
            ((__half2*)&u)[2] = __floats2half2_rn(c.x, c.y);
            ((__half2*)&u)[3] = __floats2half2_rn(c.z, c.w);
            W2h[i] = u;
        }
    }
    __syncthreads();

    int node = blockIdx.x * 32 + (threadIdx.x >> 3);
    int l = threadIdx.x & 7;

    // ---- aggregate layer 1 -> hv[8] (post-relu h1, registers) ----
    float hv[8];
#pragma unroll
    for (int j = 0; j < 8; j++) hv[j] = 0.f;

    if (node < n) {
        const uint4* t4 = (const uint4*)ht1;
        float acc[8];
#pragma unroll
        for (int j = 0; j < 8; j++) acc[j] = 0.f;
        acc_u4(acc, t4[(size_t)node * 8 + l]);   // self loop

        int k = rowptr_of(node);
        int e = k + g_degi[node];
        for (; k + 4 <= e; k += 4) {
            int s0 = g_csr[k], s1 = g_csr[k + 1];
            int s2 = g_csr[k + 2], s3 = g_csr[k + 3];
            uint4 v0 = t4[(size_t)s0 * 8 + l];
            uint4 v1 = t4[(size_t)s1 * 8 + l];
            uint4 v2 = t4[(size_t)s2 * 8 + l];
            uint4 v3 = t4[(size_t)s3 * 8 + l];
            acc_u4(acc, v0); acc_u4(acc, v1); acc_u4(acc, v2); acc_u4(acc, v3);
        }
        for (; k < e; k++) acc_u4(acc, t4[(size_t)g_csr[k] * 8 + l]);

        float ds = g_dis[node];
        const float4* b4 = (const float4*)b;
        float4 b0 = b4[l * 2], b1 = b4[l * 2 + 1];
        hv[0] = fmaxf(acc[0] * ds + b0.x, 0.f);
        hv[1] = fmaxf(acc[1] * ds + b0.y, 0.f);
        hv[2] = fmaxf(acc[2] * ds + b0.z, 0.f);
        hv[3] = fmaxf(acc[3] * ds + b0.w, 0.f);
        hv[4] = fmaxf(acc[4] * ds + b1.x, 0.f);
        hv[5] = fmaxf(acc[5] * ds + b1.y, 0.f);
        hv[6] = fmaxf(acc[6] * ds + b1.z, 0.f);
        hv[7] = fmaxf(acc[7] * ds + b1.w, 0.f);
    }

    // ---- gemv: ht2[node][8l..8l+7] = (h1[node] @ W2)[cols] * dis ----
    float ga[8];
#pragma unroll
    for (int j = 0; j < 8; j++) ga[j] = 0.f;

    for (int kb = 0; kb < 8; kb++) {
#pragma unroll
        for (int j = 0; j < 8; j++) {
            int k = kb * 8 + j;
            float xs = __shfl_sync(~0u, hv[j], kb, 8);
            uint4 wv = W2h[k * 8 + l];
            float2 w0 = __half22float2(((__half2*)&wv)[0]);
            float2 w1 = __half22float2(((__half2*)&wv)[1]);
            float2 w2 = __half22float2(((__half2*)&wv)[2]);
            float2 w3 = __half22float2(((__half2*)&wv)[3]);
            ga[0] += xs * w0.x; ga[1] += xs * w0.y;
            ga[2] += xs * w1.x; ga[3] += xs * w1.y;
            ga[4] += xs * w2.x; ga[5] += xs * w2.y;
            ga[6] += xs * w3.x; ga[7] += xs * w3.y;
        }
    }

    if (node < n) {
        float ds = g_dis[node];
        ((uint4*)((__half*)ht2 + (size_t)node * DH))[l] = pack8h(ga, ds);
    }
}

// Aggregate layer 2 + global mean pool atomics. 8 lanes/node.
__global__ void k_agg_pool(const __half2* __restrict__ ht,
                           const float* __restrict__ b,
                           const void* __restrict__ batch, int n)
{
    int t = blockIdx.x * blockDim.x + threadIdx.x;
    int node = t >> 3;
    if (node >= n) return;
    int l = t & 7;

    const uint4* t4 = (const uint4*)ht;
    float acc[8];
#pragma unroll
    for (int j = 0; j < 8; j++) acc[j] = 0.f;
    acc_u4(acc, t4[(size_t)node * 8 + l]);

    int k = rowptr_of(node);
    int e = k + g_degi[node];
    for (; k + 4 <= e; k += 4) {
        int s0 = g_csr[k], s1 = g_csr[k + 1];
        int s2 = g_csr[k + 2], s3 = g_csr[k + 3];
        uint4 v0 = t4[(size_t)s0 * 8 + l];
        uint4 v1 = t4[(size_t)s1 * 8 + l];
        uint4 v2 = t4[(size_t)s2 * 8 + l];
        uint4 v3 = t4[(size_t)s3 * 8 + l];
        acc_u4(acc, v0); acc_u4(acc, v1); acc_u4(acc, v2); acc_u4(acc, v3);
    }
    for (; k < e; k++) acc_u4(acc, t4[(size_t)g_csr[k] * 8 + l]);

    float ds = g_dis[node];
    const float4* b4 = (const float4*)b;
    float4 b0 = b4[l * 2], b1 = b4[l * 2 + 1];
    float4 r0, r1;
    r0.x = fmaxf(acc[0] * ds + b0.x, 0.f);
    r0.y = fmaxf(acc[1] * ds + b0.y, 0.f);
    r0.z = fmaxf(acc[2] * ds + b0.z, 0.f);
    r0.w = fmaxf(acc[3] * ds + b0.w, 0.f);
    r1.x = fmaxf(acc[4] * ds + b1.x, 0.f);
    r1.y = fmaxf(acc[5] * ds + b1.y, 0.f);
    r1.z = fmaxf(acc[6] * ds + b1.z, 0.f);
    r1.w = fmaxf(acc[7] * ds + b1.w, 0.f);

    int gph = load_idx(batch, node, g_is32);
    float* pp = (float*)g_pool + (size_t)gph * DH + l * 8;
    red_add_v4(pp, r0);
    red_add_v4(pp + 4, r1);
    if (l == 0) atomicAdd(&g_cnt[gph], 1.0f);
}

// out[g, c] = (pool[g] / max(cnt,1)) @ Wfc + bfc
__global__ void k_fc(const float* __restrict__ Wfc, const float* __restrict__ bfc,
                     float* __restrict__ out)
{
    int t = threadIdx.x;
    if (t >= NG * NCLS) return;
    int gph = t / NCLS, c = t % NCLS;
    float inv = 1.0f / fmaxf(g_cnt[gph], 1.0f);
    const float* pr = (const float*)g_pool + (size_t)gph * DH;
    float acc = 0.f;
#pragma unroll
    for (int j = 0; j < DH; j++) acc += pr[j] * Wfc[j * NCLS + c];
    out[t] = acc * inv + bfc[c];
}

// ---------------- launcher ----------------
extern "C" void kernel_launch(void* const* d_in, const int* in_sizes, int n_in,
                              void* d_out, int out_size)
{
    const float* x   = (const float*)d_in[0];
    const void*  ei  = d_in[1];
    const void*  bat = d_in[2];
    const float* W1  = (const float*)d_in[3];
    const float* b1  = (const float*)d_in[4];
    const float* W2  = (const float*)d_in[5];
    const float* b2  = (const float*)d_in[6];
    const float* Wfc = (const float*)d_in[7];
    const float* bfc = (const float*)d_in[8];
    float* out = (float*)d_out;

    int n = in_sizes[0] / DH;       // nodes
    int E = in_sizes[1] / 2;        // edges

    static __half2* pA1 = nullptr; static __half2* pA2 = nullptr;
    if (!pA1) {
        void* tmp;
        cudaGetSymbolAddress(&tmp, g_Ah1); pA1 = (__half2*)tmp;
        cudaGetSymbolAddress(&tmp, g_Ah2); pA2 = (__half2*)tmp;
    }

    const int TB = 256;
    int nb_scan = (n + SCAN_B - 1) / SCAN_B;
    int half_e_blocks = ((E + 1) / 2 + TB - 1) / TB;
    int gemm_blocks = (n + 127) / 128;          // 128 rows/block
    int fused_blocks = (n + 31) / 32;
    int agg_blocks = ((long long)n * 8 + TB - 1) / TB;

    k_init<<<(n + TB - 1) / TB, TB>>>(ei, n);                       // 1
    k_deg<<<half_e_blocks, TB>>>(ei, E);                            // 2
    k_scan1<<<nb_scan, SCAN_B>>>(n);                                // 3
    k_scan2_gemm1<<<1 + gemm_blocks, TB>>>(nb_scan, x, W1, pA1, n); // 4 (profiled)
    k_fill<<<half_e_blocks, TB>>>(ei, E);                           // 5
    k_agg1_gemm2<<<fused_blocks, TB>>>(pA1, b1, W2, pA2, n);        // 6
    k_agg_pool<<<agg_blocks, TB>>>(pA2, b2, bat, n);                // 7
    k_fc<<<1, NG * NCLS>>>(Wfc, bfc, out);                          // 8
}

// round 6
// speedup vs baseline: 2.2401x; 1.0537x over previous
#include <cuda_runtime.h>
#include <cuda_fp16.h>
#include <cstdint>

// ---------------- problem constants (capacities) ----------------
#define NMAX   50000
#define EMAX   1600000
#define DH     64
#define NG     64
#define NCLS   10
#define SCAN_B 256

// ---------------- device scratch (no allocations allowed) -------
// Invariant: g_degi, g_cnt2, g_pool, g_cnt are ZERO at kernel_launch entry
// (BSS zero-init on first call; restored at the tail of agg_pool / fc).
__device__ __half2 g_Ah1[NMAX * 32];     // ht1 table, fp16 (row = 128B)
__device__ __half2 g_Ah2[NMAX * 32];     // ht2 table, fp16
__device__ float   g_dis[NMAX];          // rsqrt(deg+1)
__device__ int     g_degi[NMAX];         // edge in-degree (no self loop)
__device__ int     g_rowtmp[NMAX];       // per-block exclusive scan
__device__ int     g_cnt2[NMAX];         // fill cursors (offset within row)
__device__ int     g_bsum[(NMAX + SCAN_B - 1) / SCAN_B];
__device__ int     g_csr[EMAX];          // (src << 7) byte offsets, grouped by dst
__device__ float4  g_pool[NG * 16];      // per-graph feature sums
__device__ float   g_cnt[NG];            // per-graph node counts
__device__ int     g_is32;               // 1 if indices are int32 on the wire

// ---------------- helpers ----------------
__device__ __forceinline__ int load_idx(const void* p, long long i, int is32) {
    if (is32) return ((const int*)p)[i];
    return (int)((const long long*)p)[i];
}

__device__ __forceinline__ void red_add_v4(float* addr, float4 v) {
    asm volatile("red.global.add.v4.f32 [%0], {%1,%2,%3,%4};"
                 :: "l"(addr), "f"(v.x), "f"(v.y), "f"(v.z), "f"(v.w)
                 : "memory");
}

__device__ __forceinline__ void acc_u4(float* acc, uint4 u) {
    float2 f0 = __half22float2(((__half2*)&u)[0]);
    float2 f1 = __half22float2(((__half2*)&u)[1]);
    float2 f2 = __half22float2(((__half2*)&u)[2]);
    float2 f3 = __half22float2(((__half2*)&u)[3]);
    acc[0] += f0.x; acc[1] += f0.y; acc[2] += f1.x; acc[3] += f1.y;
    acc[4] += f2.x; acc[5] += f2.y; acc[6] += f3.x; acc[7] += f3.y;
}

__device__ __forceinline__ uint4 hadd4(uint4 a, uint4 b) {
    uint4 r;
    ((__half2*)&r)[0] = __hadd2(((__half2*)&a)[0], ((__half2*)&b)[0]);
    ((__half2*)&r)[1] = __hadd2(((__half2*)&a)[1], ((__half2*)&b)[1]);
    ((__half2*)&r)[2] = __hadd2(((__half2*)&a)[2], ((__half2*)&b)[2]);
    ((__half2*)&r)[3] = __hadd2(((__half2*)&a)[3], ((__half2*)&b)[3]);
    return r;
}

// virtual rowptr
__device__ __forceinline__ int rowptr_of(int i) {
    return g_rowtmp[i] + g_bsum[i >> 8];
}

// pack 8 floats (scaled by ds) into a uint4 of halves
__device__ __forceinline__ uint4 pack8h(const float* v, float ds) {
    uint4 u;
    ((__half2*)&u)[0] = __floats2half2_rn(v[0] * ds, v[1] * ds);
    ((__half2*)&u)[1] = __floats2half2_rn(v[2] * ds, v[3] * ds);
    ((__half2*)&u)[2] = __floats2half2_rn(v[4] * ds, v[5] * ds);
    ((__half2*)&u)[3] = __floats2half2_rn(v[6] * ds, v[7] * ds);
    return u;
}

// gather helper: load 16B of a ht row by byte offset
__device__ __forceinline__ uint4 gat(const char* base, int off, int l16) {
    return *(const uint4*)(base + off + l16);
}

// ---------------- kernels ----------------

// deg[dst] += 1 over edges, 4 edges/thread; per-block dtype consensus.
__global__ void k_deg(const void* __restrict__ ei, int E) {
    __shared__ int flag;
    if (threadIdx.x == 0) flag = 0;
    __syncthreads();
    // probe first 2KB (src region under both interpretations)
    long long probe = ((const long long*)ei)[threadIdx.x];
    if ((unsigned long long)probe > 0xFFFFFFFFull) flag = 1;
    __syncthreads();
    int is32 = flag;

    int t = blockIdx.x * blockDim.x + threadIdx.x;
    if (t == 0) g_is32 = is32;
    int e = t * 4;
    if (e >= E) return;

    if (is32) {
        const int* dstp = (const int*)ei + E;
        if (e + 3 < E) {
            int4 d = ((const int4*)dstp)[t];
            atomicAdd(&g_degi[d.x], 1); atomicAdd(&g_degi[d.y], 1);
            atomicAdd(&g_degi[d.z], 1); atomicAdd(&g_degi[d.w], 1);
        } else {
            for (int i = e; i < E; i++) atomicAdd(&g_degi[dstp[i]], 1);
        }
    } else {
        const long long* dstp = (const long long*)ei + E;
        if (e + 3 < E) {
            longlong2 d0 = ((const longlong2*)dstp)[t * 2];
            longlong2 d1 = ((const longlong2*)dstp)[t * 2 + 1];
            atomicAdd(&g_degi[(int)d0.x], 1); atomicAdd(&g_degi[(int)d0.y], 1);
            atomicAdd(&g_degi[(int)d1.x], 1); atomicAdd(&g_degi[(int)d1.y], 1);
        } else {
            for (int i = e; i < E; i++) atomicAdd(&g_degi[(int)dstp[i]], 1);
        }
    }
}

// per-block exclusive scan of deg; block sums to g_bsum; dis = rsqrt(deg+1)
__global__ void k_scan1(int n) {
    __shared__ int ws[8];
    int i = blockIdx.x * SCAN_B + threadIdx.x;
    int v = (i < n) ? g_degi[i] : 0;
    int lane = threadIdx.x & 31, w = threadIdx.x >> 5;
    int x = v;
#pragma unroll
    for (int o = 1; o < 32; o <<= 1) {
        int y = __shfl_up_sync(~0u, x, o);
        if (lane >= o) x += y;
    }
    if (lane == 31) ws[w] = x;
    __syncthreads();
    if (w == 0) {
        int y = (lane < 8) ? ws[lane] : 0;
#pragma unroll
        for (int o = 1; o < 8; o <<= 1) {
            int z = __shfl_up_sync(~0u, y, o);
            if (lane >= o) y += z;
        }
        if (lane < 8) ws[lane] = y;
    }
    __syncthreads();
    int incl = x + (w > 0 ? ws[w - 1] : 0);
    if (i < n) {
        g_rowtmp[i] = incl - v;
        g_dis[i] = rsqrtf((float)(v + 1));
    }
    if (threadIdx.x == SCAN_B - 1) g_bsum[blockIdx.x] = incl;
}

// block 0: exclusive scan of block sums. blocks >= 1: gemm1 (fp32, shfl bcast).
__global__ void k_scan2_gemm1(int nb, const float* __restrict__ X,
                              const float* __restrict__ W,
                              __half2* __restrict__ ht, int n)
{
    if (blockIdx.x == 0) {
        __shared__ int ws[8];
        int lane = threadIdx.x & 31, w = threadIdx.x >> 5;
        int v = (threadIdx.x < nb) ? g_bsum[threadIdx.x] : 0;
        int x = v;
#pragma unroll
        for (int o = 1; o < 32; o <<= 1) {
            int y = __shfl_up_sync(~0u, x, o);
            if (lane >= o) x += y;
        }
        if (lane == 31) ws[w] = x;
        __syncthreads();
        if (w == 0) {
            int y = (lane < 8) ? ws[lane] : 0;
#pragma unroll
            for (int o = 1; o < 8; o <<= 1) {
                int z = __shfl_up_sync(~0u, y, o);
                if (lane >= o) y += z;
            }
            if (lane < 8) ws[lane] = y;
        }
        __syncthreads();
        int excl = x - v + (w > 0 ? ws[w - 1] : 0);
        if (threadIdx.x < nb) g_bsum[threadIdx.x] = excl;
        return;
    }

    __shared__ float4 Ws4[DH * 16];
    const float4* W4 = (const float4*)W;
    for (int i = threadIdx.x; i < DH * 16; i += blockDim.x) Ws4[i] = W4[i];
    __syncthreads();

    int grp = threadIdx.x >> 3;
    int l   = threadIdx.x & 7;
    int r0  = (blockIdx.x - 1) * 128 + grp * 4;

    float xr[4][8], acc[4][8];
#pragma unroll
    for (int r = 0; r < 4; r++)
#pragma unroll
        for (int c = 0; c < 8; c++) { acc[r][c] = 0.f; xr[r][c] = 0.f; }

#pragma unroll
    for (int r = 0; r < 4; r++) {
        int row = r0 + r;
        if (row < n) {
            const float4* xp = (const float4*)(X + (size_t)row * DH);
            float4 a = xp[l * 2];
            float4 bq = xp[l * 2 + 1];
            xr[r][0] = a.x;  xr[r][1] = a.y;  xr[r][2] = a.z;  xr[r][3] = a.w;
            xr[r][4] = bq.x; xr[r][5] = bq.y; xr[r][6] = bq.z; xr[r][7] = bq.w;
        }
    }

    for (int kb = 0; kb < 8; kb++) {
#pragma unroll
        for (int j = 0; j < 8; j++) {
            int k = kb * 8 + j;
            float4 w0 = Ws4[k * 16 + l * 2];
            float4 w1 = Ws4[k * 16 + l * 2 + 1];
            float xv0 = __shfl_sync(~0u, xr[0][j], kb, 8);
            float xv1 = __shfl_sync(~0u, xr[1][j], kb, 8);
            float xv2 = __shfl_sync(~0u, xr[2][j], kb, 8);
            float xv3 = __shfl_sync(~0u, xr[3][j], kb, 8);
#pragma unroll
            for (int r = 0; r < 4; r++) {
                float xv = (r == 0) ? xv0 : (r == 1) ? xv1 : (r == 2) ? xv2 : xv3;
                acc[r][0] += xv * w0.x; acc[r][1] += xv * w0.y;
                acc[r][2] += xv * w0.z; acc[r][3] += xv * w0.w;
                acc[r][4] += xv * w1.x; acc[r][5] += xv * w1.y;
                acc[r][6] += xv * w1.z; acc[r][7] += xv * w1.w;
            }
        }
    }

#pragma unroll
    for (int r = 0; r < 4; r++) {
        int row = r0 + r;
        if (row < n) {
            float ds = g_dis[row];
            ((uint4*)((__half*)ht + (size_t)row * DH))[l] = pack8h(acc[r], ds);
        }
    }
}

// scatter edges into CSR (byte offsets src<<7), 4 edges/thread
__global__ void k_fill(const void* __restrict__ ei, int E) {
    int t = blockIdx.x * blockDim.x + threadIdx.x;
    int e = t * 4;
    if (e >= E) return;
    int is32 = g_is32;
    int s[4], d[4], cnt;
    if (is32) {
        const int* srcp = (const int*)ei;
        const int* dstp = srcp + E;
        if (e + 3 < E) {
            int4 sv = ((const int4*)srcp)[t];
            int4 dv = ((const int4*)dstp)[t];
            s[0] = sv.x; s[1] = sv.y; s[2] = sv.z; s[3] = sv.w;
            d[0] = dv.x; d[1] = dv.y; d[2] = dv.z; d[3] = dv.w;
            cnt = 4;
        } else {
            cnt = E - e;
            for (int i = 0; i < cnt; i++) { s[i] = srcp[e + i]; d[i] = dstp[e + i]; }
        }
    } else {
        const long long* srcp = (const long long*)ei;
        const long long* dstp = srcp + E;
        if (e + 3 < E) {
            longlong2 s0 = ((const longlong2*)srcp)[t * 2];
            longlong2 s1 = ((const longlong2*)srcp)[t * 2 + 1];
            longlong2 d0 = ((const longlong2*)dstp)[t * 2];
            longlong2 d1 = ((const longlong2*)dstp)[t * 2 + 1];
            s[0] = (int)s0.x; s[1] = (int)s0.y; s[2] = (int)s1.x; s[3] = (int)s1.y;
            d[0] = (int)d0.x; d[1] = (int)d0.y; d[2] = (int)d1.x; d[3] = (int)d1.y;
            cnt = 4;
        } else {
            cnt = E - e;
            for (int i = 0; i < cnt; i++) { s[i] = (int)srcp[e + i]; d[i] = (int)dstp[e + i]; }
        }
    }
#pragma unroll
    for (int i = 0; i < 4; i++) {
        if (i < cnt) {
            int p = rowptr_of(d[i]) + atomicAdd(&g_cnt2[d[i]], 1);
            g_csr[p] = s[i] << 7;
        }
    }
}

// shared gather-sum: returns fp32 acc[8] = sum of ht rows (self + neighbors)
__device__ __forceinline__ void gather_sum(const __half2* __restrict__ ht,
                                           int node, int l, float* acc)
{
    const char* hb = (const char*)ht;
    int l16 = l << 4;
#pragma unroll
    for (int j = 0; j < 8; j++) acc[j] = 0.f;
    acc_u4(acc, gat(hb, node << 7, l16));   // self loop

    int k = rowptr_of(node);
    int e = k + g_degi[node];
    for (; k + 8 <= e; k += 8) {
        int o0 = g_csr[k],     o1 = g_csr[k + 1];
        int o2 = g_csr[k + 2], o3 = g_csr[k + 3];
        int o4 = g_csr[k + 4], o5 = g_csr[k + 5];
        int o6 = g_csr[k + 6], o7 = g_csr[k + 7];
        uint4 v0 = gat(hb, o0, l16), v1 = gat(hb, o1, l16);
        uint4 v2 = gat(hb, o2, l16), v3 = gat(hb, o3, l16);
        uint4 v4 = gat(hb, o4, l16), v5 = gat(hb, o5, l16);
        uint4 v6 = gat(hb, o6, l16), v7 = gat(hb, o7, l16);
        uint4 t0 = hadd4(hadd4(v0, v1), hadd4(v2, v3));
        uint4 t1 = hadd4(hadd4(v4, v5), hadd4(v6, v7));
        acc_u4(acc, hadd4(t0, t1));
    }
    for (; k + 4 <= e; k += 4) {
        int o0 = g_csr[k],     o1 = g_csr[k + 1];
        int o2 = g_csr[k + 2], o3 = g_csr[k + 3];
        uint4 v0 = gat(hb, o0, l16), v1 = gat(hb, o1, l16);
        uint4 v2 = gat(hb, o2, l16), v3 = gat(hb, o3, l16);
        acc_u4(acc, hadd4(hadd4(v0, v1), hadd4(v2, v3)));
    }
    for (; k < e; k++) acc_u4(acc, gat(hb, g_csr[k], l16));
}

// Fused: agg over ht1 -> h1 (regs) -> gemv W2 (fp16 hfma2) -> ht2 (fp16).
__global__ void k_agg1_gemm2(const __half2* __restrict__ ht1,
                             const float* __restrict__ b,
                             const float* __restrict__ W2,
                             __half2* __restrict__ ht2, int n)
{
    __shared__ uint4 W2h[DH * 8];   // W2[64][64] fp16, 8KB
    {
        const float4* w4 = (const float4*)W2;
        for (int i = threadIdx.x; i < DH * 8; i += blockDim.x) {
            float4 a = w4[i * 2], c = w4[i * 2 + 1];
            uint4 u;
            ((__half2*)&u)[0] = __floats2half2_rn(a.x, a.y);
            ((__half2*)&u)[1] = __floats2half2_rn(a.z, a.w);
            ((__half2*)&u)[2] = __floats2half2_rn(c.x, c.y);
            ((__half2*)&u)[3] = __floats2half2_rn(c.z, c.w);
            W2h[i] = u;
        }
    }
    __syncthreads();

    int node = blockIdx.x * 32 + (threadIdx.x >> 3);
    int l = threadIdx.x & 7;

    float hv[8];
#pragma unroll
    for (int j = 0; j < 8; j++) hv[j] = 0.f;

    if (node < n) {
        float acc[8];
        gather_sum(ht1, node, l, acc);
        float ds = g_dis[node];
        const float4* b4 = (const float4*)b;
        float4 b0 = b4[l * 2], b1 = b4[l * 2 + 1];
        hv[0] = fmaxf(acc[0] * ds + b0.x, 0.f);
        hv[1] = fmaxf(acc[1] * ds + b0.y, 0.f);
        hv[2] = fmaxf(acc[2] * ds + b0.z, 0.f);
        hv[3] = fmaxf(acc[3] * ds + b0.w, 0.f);
        hv[4] = fmaxf(acc[4] * ds + b1.x, 0.f);
        hv[5] = fmaxf(acc[5] * ds + b1.y, 0.f);
        hv[6] = fmaxf(acc[6] * ds + b1.z, 0.f);
        hv[7] = fmaxf(acc[7] * ds + b1.w, 0.f);
    }

    // gemv with fp16 accumulators, 2 split-k sets
    __half2 accA[4], accB[4];
    __half2 z = __floats2half2_rn(0.f, 0.f);
#pragma unroll
    for (int i = 0; i < 4; i++) { accA[i] = z; accB[i] = z; }

    for (int kb = 0; kb < 8; kb++) {
#pragma unroll
        for (int j = 0; j < 8; j++) {
            float xs = __shfl_sync(~0u, hv[j], kb, 8);
            __half2 xs2 = __floats2half2_rn(xs, xs);
            uint4 wv = W2h[(kb * 8 + j) * 8 + l];
            __half2* wh = (__half2*)&wv;
            if (j & 1) {
#pragma unroll
                for (int i = 0; i < 4; i++) accB[i] = __hfma2(wh[i], xs2, accB[i]);
            } else {
#pragma unroll
                for (int i = 0; i < 4; i++) accA[i] = __hfma2(wh[i], xs2, accA[i]);
            }
        }
    }

    if (node < n) {
        float ga[8];
#pragma unroll
        for (int i = 0; i < 4; i++) {
            float2 fa = __half22float2(accA[i]);
            float2 fb = __half22float2(accB[i]);
            ga[2 * i]     = fa.x + fb.x;
            ga[2 * i + 1] = fa.y + fb.y;
        }
        float ds = g_dis[node];
        ((uint4*)((__half*)ht2 + (size_t)node * DH))[l] = pack8h(ga, ds);
    }
}

// Aggregate layer 2 + pool atomics; restores degi/cnt2 to zero.
__global__ void k_agg_pool(const __half2* __restrict__ ht,
                           const float* __restrict__ b,
                           const void* __restrict__ batch, int n)
{
    int t = blockIdx.x * blockDim.x + threadIdx.x;
    int node = t >> 3;
    if (node >= n) return;
    int l = t & 7;

    float acc[8];
    gather_sum(ht, node, l, acc);

    float ds = g_dis[node];
    const float4* b4 = (const float4*)b;
    float4 b0 = b4[l * 2], b1 = b4[l * 2 + 1];
    float4 r0, r1;
    r0.x = fmaxf(acc[0] * ds + b0.x, 0.f);
    r0.y = fmaxf(acc[1] * ds + b0.y, 0.f);
    r0.z = fmaxf(acc[2] * ds + b0.z, 0.f);
    r0.w = fmaxf(acc[3] * ds + b0.w, 0.f);
    r1.x = fmaxf(acc[4] * ds + b1.x, 0.f);
    r1.y = fmaxf(acc[5] * ds + b1.y, 0.f);
    r1.z = fmaxf(acc[6] * ds + b1.z, 0.f);
    r1.w = fmaxf(acc[7] * ds + b1.w, 0.f);

    int gph = load_idx(batch, node, g_is32);
    float* pp = (float*)g_pool + (size_t)gph * DH + l * 8;
    red_add_v4(pp, r0);
    red_add_v4(pp + 4, r1);
    if (l == 0) {
        atomicAdd(&g_cnt[gph], 1.0f);
        g_degi[node] = 0;    // restore zero-state for next launch
        g_cnt2[node] = 0;
    }
}

// out[g, c] = (pool[g] / max(cnt,1)) @ Wfc + bfc; restores pool/cnt to zero.
// Launch with exactly NG*NCLS = 640 threads.
__global__ void k_fc(const float* __restrict__ Wfc, const float* __restrict__ bfc,
                     float* __restrict__ out)
{
    int t = threadIdx.x;
    int gph = t / NCLS, c = t % NCLS;
    float inv = 1.0f / fmaxf(g_cnt[gph], 1.0f);
    const float* pr = (const float*)g_pool + (size_t)gph * DH;
    float acc = 0.f;
#pragma unroll
    for (int j = 0; j < DH; j++) acc += pr[j] * Wfc[j * NCLS + c];
    out[t] = acc * inv + bfc[c];

    __syncthreads();   // all reads of pool/cnt done
    for (int i = t; i < NG * 16; i += blockDim.x)
        g_pool[i] = make_float4(0.f, 0.f, 0.f, 0.f);
    if (t < NG) g_cnt[t] = 0.0f;
}

// ---------------- launcher ----------------
extern "C" void kernel_launch(void* const* d_in, const int* in_sizes, int n_in,
                              void* d_out, int out_size)
{
    const float* x   = (const float*)d_in[0];
    const void*  ei  = d_in[1];
    const void*  bat = d_in[2];
    const float* W1  = (const float*)d_in[3];
    const float* b1  = (const float*)d_in[4];
    const float* W2  = (const float*)d_in[5];
    const float* b2  = (const float*)d_in[6];
    const float* Wfc = (const float*)d_in[7];
    const float* bfc = (const float*)d_in[8];
    float* out = (float*)d_out;

    int n = in_sizes[0] / DH;       // nodes
    int E = in_sizes[1] / 2;        // edges

    static __half2* pA1 = nullptr; static __half2* pA2 = nullptr;
    if (!pA1) {
        void* tmp;
        cudaGetSymbolAddress(&tmp, g_Ah1); pA1 = (__half2*)tmp;
        cudaGetSymbolAddress(&tmp, g_Ah2); pA2 = (__half2*)tmp;
    }

    const int TB = 256;
    int nb_scan = (n + SCAN_B - 1) / SCAN_B;
    int q_e_blocks = ((E + 3) / 4 + TB - 1) / TB;
    int gemm_blocks = (n + 127) / 128;
    int fused_blocks = (n + 31) / 32;
    int agg_blocks = ((long long)n * 8 + TB - 1) / TB;

    k_deg<<<q_e_blocks, TB>>>(ei, E);                               // 1
    k_scan1<<<nb_scan, SCAN_B>>>(n);                                // 2
    k_scan2_gemm1<<<1 + gemm_blocks, TB>>>(nb_scan, x, W1, pA1, n); // 3
    k_fill<<<q_e_blocks, TB>>>(ei, E);                              // 4 (profiled)
    k_agg1_gemm2<<<fused_blocks, TB>>>(pA1, b1, W2, pA2, n);        // 5
    k_agg_pool<<<agg_blocks, TB>>>(pA2, b2, bat, n);                // 6
    k_fc<<<1, NG * NCLS>>>(Wfc, bfc, out);                          // 7
}